// round 2
// baseline (speedup 1.0000x reference)
#include <cuda_runtime.h>
#include <cuda_bf16.h>

#define N_NODES 50000
#define N_EDGES 800000
#define N_LABEL 200000
#define HID_CH 128
#define OUT_CH 64

// ---------------- scratch (device globals; no allocation allowed) ----------
__device__ __align__(16) float g_deg[N_NODES];
__device__ __align__(16) float g_dis[N_NODES];    // deg^-1/2
__device__ __align__(16) float g_dinv[N_NODES];   // deg^-1
__device__ __align__(16) float g_h[N_NODES * HID_CH];     // x @ W1
__device__ __align__(16) float g_agg1[N_NODES * HID_CH];  // scatter target / h1
__device__ __align__(16) float g_z[N_NODES * OUT_CH];     // h1 @ W2, then final z
__device__ __align__(16) float g_agg2[N_NODES * OUT_CH];

// ---------------- vector reductions ----------------------------------------
__device__ __forceinline__ void red_add_f32x4(float4* p, float4 v) {
    asm volatile("red.global.add.v4.f32 [%0], {%1, %2, %3, %4};"
                 :: "l"(p), "f"(v.x), "f"(v.y), "f"(v.z), "f"(v.w) : "memory");
}
__device__ __forceinline__ void red_add_f32x2(float2* p, float2 v) {
    asm volatile("red.global.add.v2.f32 [%0], {%1, %2};"
                 :: "l"(p), "f"(v.x), "f"(v.y) : "memory");
}

// ---------------- init: zero agg buffers, deg = 1 --------------------------
__global__ void k_init() {
    int i = blockIdx.x * blockDim.x + threadIdx.x;
    const int n1 = N_NODES * HID_CH / 4;   // 1,600,000 float4
    const int n2 = N_NODES * OUT_CH / 4;   //   800,000 float4
    float4 z = make_float4(0.f, 0.f, 0.f, 0.f);
    if (i < n1)                ((float4*)g_agg1)[i] = z;
    else if (i < n1 + n2)      ((float4*)g_agg2)[i - n1] = z;
    else if (i < n1 + n2 + N_NODES) g_deg[i - n1 - n2] = 1.0f;
}

// ---------------- degree count ----------------------------------------------
__global__ void k_deg(const int* __restrict__ col) {
    int e = blockIdx.x * blockDim.x + threadIdx.x;
    if (e < N_EDGES) atomicAdd(&g_deg[col[e]], 1.0f);
}

__global__ void k_norm() {
    int i = blockIdx.x * blockDim.x + threadIdx.x;
    if (i < N_NODES) {
        float d = g_deg[i];
        g_dis[i]  = rsqrtf(d);
        g_dinv[i] = 1.0f / d;
    }
}

// ---------------- GEMM: Y[M,N] = X[M,128] @ W[128,N] ------------------------
// 256 threads/block. N=128 -> 32 rows/block; N=64 -> 64 rows/block.
template <int N>
__global__ void k_gemm(const float* __restrict__ X, const float* __restrict__ W,
                       float* __restrict__ Y) {
    constexpr int TILE_M   = (N == 128) ? 32 : 64;
    constexpr int ROWS_PER = TILE_M / 32;
    constexpr int LDX      = 129;
    extern __shared__ float smem[];
    float* sW = smem;                // 128 * N floats
    float* sX = smem + 128 * N;      // TILE_M * LDX floats

    const int tid = threadIdx.x;
    const int m0  = blockIdx.x * TILE_M;

    // stage W (coalesced float4)
    {
        const float4* W4 = (const float4*)W;
        float4* sW4 = (float4*)sW;
        #pragma unroll
        for (int i = tid; i < 128 * N / 4; i += 256) sW4[i] = W4[i];
    }
    // stage X tile (float4 global loads, scalar smem stores w/ padded stride)
    {
        constexpr int CHUNKS = TILE_M * 32;  // float4 chunks per tile
        #pragma unroll
        for (int i = tid; i < CHUNKS; i += 256) {
            int rr = i >> 5, kk = i & 31;
            int gr = m0 + rr;
            float4 v = (gr < N_NODES) ? ((const float4*)X)[gr * 32 + kk]
                                      : make_float4(0.f, 0.f, 0.f, 0.f);
            float* d = sX + rr * LDX + kk * 4;
            d[0] = v.x; d[1] = v.y; d[2] = v.z; d[3] = v.w;
        }
    }
    __syncthreads();

    const int lane = tid & 31;
    const int w    = tid >> 5;
    const int row  = lane + 32 * (w % ROWS_PER);
    const int cg   = w / ROWS_PER;   // column group of 16

    float acc[16];
    #pragma unroll
    for (int j = 0; j < 16; j++) acc[j] = 0.f;

    const float4* sW4 = (const float4*)sW;
    const float* xrow = sX + row * LDX;

    #pragma unroll 8
    for (int k = 0; k < 128; k++) {
        float xv = xrow[k];
        int base = k * (N / 4) + cg * 4;
        float4 w0 = sW4[base + 0];
        float4 w1 = sW4[base + 1];
        float4 w2 = sW4[base + 2];
        float4 w3 = sW4[base + 3];
        acc[ 0] += xv * w0.x; acc[ 1] += xv * w0.y; acc[ 2] += xv * w0.z; acc[ 3] += xv * w0.w;
        acc[ 4] += xv * w1.x; acc[ 5] += xv * w1.y; acc[ 6] += xv * w1.z; acc[ 7] += xv * w1.w;
        acc[ 8] += xv * w2.x; acc[ 9] += xv * w2.y; acc[10] += xv * w2.z; acc[11] += xv * w2.w;
        acc[12] += xv * w3.x; acc[13] += xv * w3.y; acc[14] += xv * w3.z; acc[15] += xv * w3.w;
    }

    int gr = m0 + row;
    if (gr < N_NODES) {
        float4* Y4 = (float4*)(Y + gr * N + cg * 16);
        Y4[0] = make_float4(acc[ 0], acc[ 1], acc[ 2], acc[ 3]);
        Y4[1] = make_float4(acc[ 4], acc[ 5], acc[ 6], acc[ 7]);
        Y4[2] = make_float4(acc[ 8], acc[ 9], acc[10], acc[11]);
        Y4[3] = make_float4(acc[12], acc[13], acc[14], acc[15]);
    }
}

// ---------------- edge scatter, layer 1 (128 ch): warp per edge ------------
__global__ void k_scatter128(const int* __restrict__ row,
                             const int* __restrict__ col) {
    unsigned t = blockIdx.x * blockDim.x + threadIdx.x;
    unsigned e = t >> 5;
    if (e >= N_EDGES) return;
    int lane = threadIdx.x & 31;
    int r = __ldg(row + e);
    int c = __ldg(col + e);
    float norm = g_dis[r] * g_dis[c];
    float4 v = ((const float4*)g_h)[r * 32 + lane];
    v.x *= norm; v.y *= norm; v.z *= norm; v.w *= norm;
    red_add_f32x4(((float4*)g_agg1) + c * 32 + lane, v);
}

// ---------------- combine layer 1: h1 = relu(agg1 + h*dinv + b1) -----------
__global__ void k_combine1(const float* __restrict__ b1) {
    int i = blockIdx.x * blockDim.x + threadIdx.x;  // float4 index
    if (i >= N_NODES * 32) return;
    int node = i >> 5;
    float di = g_dinv[node];
    float4 a = ((float4*)g_agg1)[i];
    float4 h = ((const float4*)g_h)[i];
    float4 b = ((const float4*)b1)[i & 31];
    float4 r;
    r.x = fmaxf(fmaf(h.x, di, a.x) + b.x, 0.f);
    r.y = fmaxf(fmaf(h.y, di, a.y) + b.y, 0.f);
    r.z = fmaxf(fmaf(h.z, di, a.z) + b.z, 0.f);
    r.w = fmaxf(fmaf(h.w, di, a.w) + b.w, 0.f);
    ((float4*)g_agg1)[i] = r;
}

// ---------------- edge scatter, layer 2 (64 ch): warp per edge -------------
__global__ void k_scatter64(const int* __restrict__ row,
                            const int* __restrict__ col) {
    unsigned t = blockIdx.x * blockDim.x + threadIdx.x;
    unsigned e = t >> 5;
    if (e >= N_EDGES) return;
    int lane = threadIdx.x & 31;
    int r = __ldg(row + e);
    int c = __ldg(col + e);
    float norm = g_dis[r] * g_dis[c];
    float2 v = ((const float2*)g_z)[r * 32 + lane];
    v.x *= norm; v.y *= norm;
    red_add_f32x2(((float2*)g_agg2) + c * 32 + lane, v);
}

// ---------------- combine layer 2: z = agg2 + z*dinv + b2 (no relu) --------
__global__ void k_combine2(const float* __restrict__ b2) {
    int i = blockIdx.x * blockDim.x + threadIdx.x;  // float4 index
    if (i >= N_NODES * 16) return;
    int node = i >> 4;
    float di = g_dinv[node];
    float4 a = ((const float4*)g_agg2)[i];
    float4 z = ((float4*)g_z)[i];
    float4 b = ((const float4*)b2)[i & 15];
    float4 r;
    r.x = fmaf(z.x, di, a.x) + b.x;
    r.y = fmaf(z.y, di, a.y) + b.y;
    r.z = fmaf(z.z, di, a.z) + b.z;
    r.w = fmaf(z.w, di, a.w) + b.w;
    ((float4*)g_z)[i] = r;
}

// ---------------- decode: out[e] = dot(z[src], z[dst]) ---------------------
__global__ void k_decode(const int* __restrict__ src,
                         const int* __restrict__ dst,
                         float* __restrict__ out) {
    unsigned t = blockIdx.x * blockDim.x + threadIdx.x;
    unsigned e = t >> 5;
    if (e >= N_LABEL) return;
    int lane = threadIdx.x & 31;
    int s = __ldg(src + e);
    int d = __ldg(dst + e);
    float2 a = ((const float2*)g_z)[s * 32 + lane];
    float2 b = ((const float2*)g_z)[d * 32 + lane];
    float p = a.x * b.x + a.y * b.y;
    #pragma unroll
    for (int o = 16; o; o >>= 1) p += __shfl_xor_sync(0xffffffffu, p, o);
    if (lane == 0) out[e] = p;
}

// ---------------- launch ----------------------------------------------------
extern "C" void kernel_launch(void* const* d_in, const int* in_sizes, int n_in,
                              void* d_out, int out_size) {
    const float* x  = (const float*)d_in[0];
    const float* W1 = (const float*)d_in[1];
    const float* b1 = (const float*)d_in[2];
    const float* W2 = (const float*)d_in[3];
    const float* b2 = (const float*)d_in[4];
    const int* edge_index = (const int*)d_in[5];
    const int* edge_label = (const int*)d_in[6];
    float* out = (float*)d_out;

    const int* erow = edge_index;
    const int* ecol = edge_index + N_EDGES;
    const int* lsrc = edge_label;
    const int* ldst = edge_label + N_LABEL;

    float *ph, *pagg1, *pz;
    cudaGetSymbolAddress((void**)&ph,    g_h);
    cudaGetSymbolAddress((void**)&pagg1, g_agg1);
    cudaGetSymbolAddress((void**)&pz,    g_z);

    const int smem128 = (128 * 128 + 32 * 129) * sizeof(float);  // 82048
    const int smem64  = (128 * 64  + 64 * 129) * sizeof(float);  // 65792
    cudaFuncSetAttribute(k_gemm<128>, cudaFuncAttributeMaxDynamicSharedMemorySize, smem128);
    cudaFuncSetAttribute(k_gemm<64>,  cudaFuncAttributeMaxDynamicSharedMemorySize, smem64);

    // 1. init (zero aggs, deg = 1)
    {
        int total = N_NODES * HID_CH / 4 + N_NODES * OUT_CH / 4 + N_NODES;
        k_init<<<(total + 255) / 256, 256>>>();
    }
    // 2. degree
    k_deg<<<(N_EDGES + 255) / 256, 256>>>(ecol);
    // 3. normalization factors
    k_norm<<<(N_NODES + 255) / 256, 256>>>();
    // 4. h = x @ W1
    k_gemm<128><<<(N_NODES + 31) / 32, 256, smem128>>>(x, W1, ph);
    // 5. scatter layer 1
    k_scatter128<<<(N_EDGES * 32 + 255) / 256, 256>>>(erow, ecol);
    // 6. h1 = relu(agg1 + h*dinv + b1)  (in place into g_agg1)
    k_combine1<<<(N_NODES * 32 + 255) / 256, 256>>>(b1);
    // 7. z = h1 @ W2
    k_gemm<64><<<(N_NODES + 63) / 64, 256, smem64>>>(pagg1, W2, pz);
    // 8. scatter layer 2
    k_scatter64<<<(N_EDGES * 32 + 255) / 256, 256>>>(erow, ecol);
    // 9. z = agg2 + z*dinv + b2  (in place into g_z)
    k_combine2<<<(N_NODES * 16 + 255) / 256, 256>>>(b2);
    // 10. decode dot products
    k_decode<<<(N_LABEL * 32 + 255) / 256, 256>>>(lsrc, ldst, out);
}

// round 3
// speedup vs baseline: 1.1402x; 1.1402x over previous
#include <cuda_runtime.h>

#define N_NODES 50000
#define N_EDGES 800000
#define N_LABEL 200000

// ---------------- scratch (device globals; no allocation allowed) ----------
__device__ int   g_degi[N_NODES];
__device__ int   g_off[N_NODES + 1];
__device__ int   g_cur[N_NODES];
__device__ float g_dis[N_NODES];     // (deg+1)^-1/2
__device__ float g_dinv[N_NODES];    // (deg+1)^-1
__device__ __align__(16) int2  g_csr[N_EDGES];        // (src_row, norm bits)
__device__ __align__(16) float g_h [N_NODES * 128];   // x @ W1
__device__ __align__(16) float g_h1[N_NODES * 128];   // relu(aggregated)
__device__ __align__(16) float g_z [N_NODES * 64];    // h1 @ W2
__device__ __align__(16) float g_zf[N_NODES * 64];    // final embeddings

// ---------------- degree ----------------------------------------------------
__global__ void k_zero() {
    int i = blockIdx.x * blockDim.x + threadIdx.x;
    if (i < N_NODES) g_degi[i] = 0;
}

__global__ void k_deg(const int* __restrict__ col) {
    int e = blockIdx.x * blockDim.x + threadIdx.x;
    if (e < N_EDGES) atomicAdd(&g_degi[col[e]], 1);
}

// ---------------- prefix scan (1 block) + norm factors ----------------------
__global__ void k_scan() {
    __shared__ int ps[1024];
    const int CH = 49;  // ceil(50000/1024)
    int t = threadIdx.x;
    int start = t * CH;
    int end = start + CH; if (end > N_NODES) end = N_NODES;
    int s = 0;
    for (int i = start; i < end; i++) s += g_degi[i];
    ps[t] = s;
    __syncthreads();
    for (int off = 1; off < 1024; off <<= 1) {
        int v = (t >= off) ? ps[t - off] : 0;
        __syncthreads();
        ps[t] += v;
        __syncthreads();
    }
    int run = (t == 0) ? 0 : ps[t - 1];
    for (int i = start; i < end; i++) {
        int d = g_degi[i];
        g_off[i] = run;
        g_cur[i] = run;
        run += d;
        float df = (float)d + 1.0f;
        g_dis[i]  = rsqrtf(df);
        g_dinv[i] = 1.0f / df;
    }
    if (t == 1023) g_off[N_NODES] = run;
}

// ---------------- CSR fill (counting sort by col) ---------------------------
__global__ void k_fill(const int* __restrict__ row, const int* __restrict__ col) {
    int e = blockIdx.x * blockDim.x + threadIdx.x;
    if (e >= N_EDGES) return;
    int r = row[e], c = col[e];
    float nm = g_dis[r] * g_dis[c];
    int pos = atomicAdd(&g_cur[c], 1);
    g_csr[pos] = make_int2(r, __float_as_int(nm));
}

// ---------------- register-tiled GEMM: Y[M,N] = X[M,128] @ W[128,N] ---------
// 256 threads, tile 128 rows. Per thread: 8 rows x (N==128 ? 8 : 4) cols.
// a-loads: warp-broadcast scalar LDS. b-loads: conflict-free LDS.128.
template <int N>
__global__ __launch_bounds__(256) void k_gemm(const float* __restrict__ X,
                                              const float* __restrict__ W,
                                              float* __restrict__ Y) {
    constexpr int TILE_M = 128;
    constexpr int LDX = 132;
    constexpr int TN = (N == 128) ? 8 : 4;
    extern __shared__ float smem[];
    float* sW = smem;                 // 128 * N
    float* sX = smem + 128 * N;       // 128 * 132

    const int tid = threadIdx.x;
    const int m0  = blockIdx.x * TILE_M;

    {   // stage W
        const float4* W4 = (const float4*)W;
        float4* sW4 = (float4*)sW;
        #pragma unroll
        for (int i = tid; i < 128 * N / 4; i += 256) sW4[i] = W4[i];
    }
    {   // stage X tile (row-major, padded stride)
        #pragma unroll
        for (int i = tid; i < TILE_M * 32; i += 256) {
            int rr = i >> 5, kk = i & 31;
            int gr = m0 + rr;
            float4 v = (gr < N_NODES) ? ((const float4*)X)[gr * 32 + kk]
                                      : make_float4(0.f, 0.f, 0.f, 0.f);
            *(float4*)(sX + rr * LDX + kk * 4) = v;
        }
    }
    __syncthreads();

    const int tn = tid & 15;
    const int tm = tid >> 4;

    float acc[8][TN];
    #pragma unroll
    for (int i = 0; i < 8; i++)
        #pragma unroll
        for (int j = 0; j < TN; j++) acc[i][j] = 0.f;

    const float4* sW4 = (const float4*)sW;
    const float*  xb  = sX + tm * 8 * LDX;

    #pragma unroll 4
    for (int k = 0; k < 128; k++) {
        float a[8];
        #pragma unroll
        for (int i = 0; i < 8; i++) a[i] = xb[i * LDX + k];
        if constexpr (N == 128) {
            float4 b0 = sW4[k * 32 + tn];        // cols tn*4 .. tn*4+3
            float4 b1 = sW4[k * 32 + tn + 16];   // cols 64+tn*4 .. 64+tn*4+3
            #pragma unroll
            for (int i = 0; i < 8; i++) {
                acc[i][0] = fmaf(a[i], b0.x, acc[i][0]);
                acc[i][1] = fmaf(a[i], b0.y, acc[i][1]);
                acc[i][2] = fmaf(a[i], b0.z, acc[i][2]);
                acc[i][3] = fmaf(a[i], b0.w, acc[i][3]);
                acc[i][4] = fmaf(a[i], b1.x, acc[i][4]);
                acc[i][5] = fmaf(a[i], b1.y, acc[i][5]);
                acc[i][6] = fmaf(a[i], b1.z, acc[i][6]);
                acc[i][7] = fmaf(a[i], b1.w, acc[i][7]);
            }
        } else {
            float4 b0 = sW4[k * 16 + tn];        // cols tn*4 .. tn*4+3
            #pragma unroll
            for (int i = 0; i < 8; i++) {
                acc[i][0] = fmaf(a[i], b0.x, acc[i][0]);
                acc[i][1] = fmaf(a[i], b0.y, acc[i][1]);
                acc[i][2] = fmaf(a[i], b0.z, acc[i][2]);
                acc[i][3] = fmaf(a[i], b0.w, acc[i][3]);
            }
        }
    }

    #pragma unroll
    for (int i = 0; i < 8; i++) {
        int gr = m0 + tm * 8 + i;
        if (gr < N_NODES) {
            *(float4*)(Y + gr * N + tn * 4) =
                make_float4(acc[i][0], acc[i][1], acc[i][2], acc[i][3]);
            if constexpr (N == 128)
                *(float4*)(Y + gr * N + 64 + tn * 4) =
                    make_float4(acc[i][4], acc[i][5], acc[i][6], acc[i][7]);
        }
    }
}

// ---------------- layer-1 aggregation: warp per node, 128 ch ----------------
// h1 = relu( sum_e norm_e * h[row_e] + h[node]*dinv + b1 )
__global__ void k_agg1(const float* __restrict__ b1) {
    int w = (blockIdx.x * blockDim.x + threadIdx.x) >> 5;
    if (w >= N_NODES) return;
    int lane = threadIdx.x & 31;
    int beg = g_off[w], end = g_off[w + 1];
    const float4* h4 = (const float4*)g_h;
    float4 acc = make_float4(0.f, 0.f, 0.f, 0.f);

    for (int base = beg; base < end; base += 32) {
        int n = end - base; if (n > 32) n = 32;
        int2 ed = make_int2(0, 0);
        if (base + lane < end) ed = g_csr[base + lane];
        int j = 0;
        for (; j + 2 <= n; j += 2) {
            int   r0 = __shfl_sync(0xffffffffu, ed.x, j);
            float m0 = __int_as_float(__shfl_sync(0xffffffffu, ed.y, j));
            int   r1 = __shfl_sync(0xffffffffu, ed.x, j + 1);
            float m1 = __int_as_float(__shfl_sync(0xffffffffu, ed.y, j + 1));
            float4 v0 = h4[r0 * 32 + lane];
            float4 v1 = h4[r1 * 32 + lane];
            acc.x = fmaf(v0.x, m0, fmaf(v1.x, m1, acc.x));
            acc.y = fmaf(v0.y, m0, fmaf(v1.y, m1, acc.y));
            acc.z = fmaf(v0.z, m0, fmaf(v1.z, m1, acc.z));
            acc.w = fmaf(v0.w, m0, fmaf(v1.w, m1, acc.w));
        }
        if (j < n) {
            int   r0 = __shfl_sync(0xffffffffu, ed.x, j);
            float m0 = __int_as_float(__shfl_sync(0xffffffffu, ed.y, j));
            float4 v0 = h4[r0 * 32 + lane];
            acc.x = fmaf(v0.x, m0, acc.x);
            acc.y = fmaf(v0.y, m0, acc.y);
            acc.z = fmaf(v0.z, m0, acc.z);
            acc.w = fmaf(v0.w, m0, acc.w);
        }
    }
    float di = g_dinv[w];
    float4 hs = h4[w * 32 + lane];
    float4 bb = ((const float4*)b1)[lane];
    float4 o;
    o.x = fmaxf(fmaf(hs.x, di, acc.x) + bb.x, 0.f);
    o.y = fmaxf(fmaf(hs.y, di, acc.y) + bb.y, 0.f);
    o.z = fmaxf(fmaf(hs.z, di, acc.z) + bb.z, 0.f);
    o.w = fmaxf(fmaf(hs.w, di, acc.w) + bb.w, 0.f);
    ((float4*)g_h1)[w * 32 + lane] = o;
}

// ---------------- layer-2 aggregation: warp per node, 64 ch -----------------
__global__ void k_agg2(const float* __restrict__ b2) {
    int w = (blockIdx.x * blockDim.x + threadIdx.x) >> 5;
    if (w >= N_NODES) return;
    int lane = threadIdx.x & 31;
    int beg = g_off[w], end = g_off[w + 1];
    const float2* z2 = (const float2*)g_z;
    float2 acc = make_float2(0.f, 0.f);

    for (int base = beg; base < end; base += 32) {
        int n = end - base; if (n > 32) n = 32;
        int2 ed = make_int2(0, 0);
        if (base + lane < end) ed = g_csr[base + lane];
        int j = 0;
        for (; j + 2 <= n; j += 2) {
            int   r0 = __shfl_sync(0xffffffffu, ed.x, j);
            float m0 = __int_as_float(__shfl_sync(0xffffffffu, ed.y, j));
            int   r1 = __shfl_sync(0xffffffffu, ed.x, j + 1);
            float m1 = __int_as_float(__shfl_sync(0xffffffffu, ed.y, j + 1));
            float2 v0 = z2[r0 * 32 + lane];
            float2 v1 = z2[r1 * 32 + lane];
            acc.x = fmaf(v0.x, m0, fmaf(v1.x, m1, acc.x));
            acc.y = fmaf(v0.y, m0, fmaf(v1.y, m1, acc.y));
        }
        if (j < n) {
            int   r0 = __shfl_sync(0xffffffffu, ed.x, j);
            float m0 = __int_as_float(__shfl_sync(0xffffffffu, ed.y, j));
            float2 v0 = z2[r0 * 32 + lane];
            acc.x = fmaf(v0.x, m0, acc.x);
            acc.y = fmaf(v0.y, m0, acc.y);
        }
    }
    float di = g_dinv[w];
    float2 zs = z2[w * 32 + lane];
    float2 bb = ((const float2*)b2)[lane];
    float2 o;
    o.x = fmaf(zs.x, di, acc.x) + bb.x;
    o.y = fmaf(zs.y, di, acc.y) + bb.y;
    ((float2*)g_zf)[w * 32 + lane] = o;
}

// ---------------- decode: 16-lane group per label edge ----------------------
__global__ void k_decode(const int* __restrict__ src, const int* __restrict__ dst,
                         float* __restrict__ out) {
    int t = blockIdx.x * blockDim.x + threadIdx.x;
    int e = t >> 4;
    if (e >= N_LABEL) return;
    int sub = t & 15;
    int s = __ldg(src + e);
    int d = __ldg(dst + e);
    const float4* z4 = (const float4*)g_zf;
    float4 a = z4[s * 16 + sub];
    float4 b = z4[d * 16 + sub];
    float p = a.x * b.x + a.y * b.y + a.z * b.z + a.w * b.w;
    p += __shfl_xor_sync(0xffffffffu, p, 8, 16);
    p += __shfl_xor_sync(0xffffffffu, p, 4, 16);
    p += __shfl_xor_sync(0xffffffffu, p, 2, 16);
    p += __shfl_xor_sync(0xffffffffu, p, 1, 16);
    if (sub == 0) out[e] = p;
}

// ---------------- launch ----------------------------------------------------
extern "C" void kernel_launch(void* const* d_in, const int* in_sizes, int n_in,
                              void* d_out, int out_size) {
    const float* x  = (const float*)d_in[0];
    const float* W1 = (const float*)d_in[1];
    const float* b1 = (const float*)d_in[2];
    const float* W2 = (const float*)d_in[3];
    const float* b2 = (const float*)d_in[4];
    const int* edge_index = (const int*)d_in[5];
    const int* edge_label = (const int*)d_in[6];
    float* out = (float*)d_out;

    const int* erow = edge_index;
    const int* ecol = edge_index + N_EDGES;
    const int* lsrc = edge_label;
    const int* ldst = edge_label + N_LABEL;

    float *ph, *ph1, *pz;
    cudaGetSymbolAddress((void**)&ph,  g_h);
    cudaGetSymbolAddress((void**)&ph1, g_h1);
    cudaGetSymbolAddress((void**)&pz,  g_z);

    const int smem128 = (128 * 128 + 128 * 132) * sizeof(float);  // 133120
    const int smem64  = (128 * 64  + 128 * 132) * sizeof(float);  // 100352
    cudaFuncSetAttribute(k_gemm<128>, cudaFuncAttributeMaxDynamicSharedMemorySize, smem128);
    cudaFuncSetAttribute(k_gemm<64>,  cudaFuncAttributeMaxDynamicSharedMemorySize, smem64);

    // CSR build
    k_zero<<<(N_NODES + 255) / 256, 256>>>();
    k_deg<<<(N_EDGES + 255) / 256, 256>>>(ecol);
    k_scan<<<1, 1024>>>();
    k_fill<<<(N_EDGES + 255) / 256, 256>>>(erow, ecol);
    // layer 1
    k_gemm<128><<<(N_NODES + 127) / 128, 256, smem128>>>(x, W1, ph);
    k_agg1<<<(N_NODES * 32 + 255) / 256, 256>>>(b1);
    // layer 2
    k_gemm<64><<<(N_NODES + 127) / 128, 256, smem64>>>(ph1, W2, pz);
    k_agg2<<<(N_NODES * 32 + 255) / 256, 256>>>(b2);
    // decode
    k_decode<<<(N_LABEL * 16 + 255) / 256, 256>>>(lsrc, ldst, out);
}

// round 4
// speedup vs baseline: 2.0036x; 1.7573x over previous
#include <cuda_runtime.h>

#define N_NODES 50000
#define N_EDGES 800000
#define N_LABEL 200000
#define NBLK 196           // ceil(50000/256)

// ---------------- scratch (device globals; no allocation allowed) ----------
__device__ int   g_degi[N_NODES];
__device__ int   g_off[N_NODES + 1];
__device__ int   g_cur[N_NODES];
__device__ float g_dis[N_NODES];     // (deg+1)^-1/2
__device__ int   g_bsum[256];
__device__ int   g_bpre[256];
__device__ __align__(16) int   g_csr[N_EDGES];        // src row only
__device__ __align__(16) float g_h [N_NODES * 128];   // (x @ W1) * dis[row]
__device__ __align__(16) float g_h1[N_NODES * 128];   // relu layer-1 output
__device__ __align__(16) float g_z [N_NODES * 64];    // (h1 @ W2) * dis[row]
__device__ __align__(16) float g_zf[N_NODES * 64];    // final embeddings

// ---------------- degree ----------------------------------------------------
__global__ void k_zero() {
    int i = blockIdx.x * blockDim.x + threadIdx.x;
    if (i < N_NODES) g_degi[i] = 0;
}

__global__ void k_deg(const int* __restrict__ col) {
    int e = blockIdx.x * blockDim.x + threadIdx.x;
    if (e < N_EDGES) atomicAdd(&g_degi[col[e]], 1);
}

// ---------------- scan stage A: per-block sums -------------------------------
__global__ void k_scanA() {
    int t = threadIdx.x, b = blockIdx.x;
    int i = b * 256 + t;
    int d = (i < N_NODES) ? g_degi[i] : 0;
    // warp reduce
    int v = d;
    #pragma unroll
    for (int o = 16; o; o >>= 1) v += __shfl_xor_sync(0xffffffffu, v, o);
    __shared__ int ws[8];
    if ((t & 31) == 0) ws[t >> 5] = v;
    __syncthreads();
    if (t == 0) {
        int s = 0;
        #pragma unroll
        for (int k = 0; k < 8; k++) s += ws[k];
        g_bsum[b] = s;
    }
}

// ---------------- scan stage B: scan block sums (1 block) --------------------
__global__ void k_scanB() {
    int t = threadIdx.x;
    int d = (t < NBLK) ? g_bsum[t] : 0;
    int lane = t & 31, wid = t >> 5;
    int v = d;
    #pragma unroll
    for (int o = 1; o < 32; o <<= 1) {
        int u = __shfl_up_sync(0xffffffffu, v, o);
        if (lane >= o) v += u;
    }
    __shared__ int ws[8];
    if (lane == 31) ws[wid] = v;
    __syncthreads();
    if (t == 0) {
        int run = 0;
        #pragma unroll
        for (int k = 0; k < 8; k++) { int tmp = ws[k]; ws[k] = run; run += tmp; }
    }
    __syncthreads();
    if (t < NBLK) g_bpre[t] = ws[wid] + (v - d);   // exclusive prefix
}

// ---------------- scan stage C: offsets + norm factors -----------------------
__global__ void k_scanC() {
    int t = threadIdx.x, b = blockIdx.x;
    int i = b * 256 + t;
    int d = (i < N_NODES) ? g_degi[i] : 0;
    int lane = t & 31, wid = t >> 5;
    int v = d;
    #pragma unroll
    for (int o = 1; o < 32; o <<= 1) {
        int u = __shfl_up_sync(0xffffffffu, v, o);
        if (lane >= o) v += u;
    }
    __shared__ int ws[8];
    if (lane == 31) ws[wid] = v;
    __syncthreads();
    if (t == 0) {
        int run = 0;
        #pragma unroll
        for (int k = 0; k < 8; k++) { int tmp = ws[k]; ws[k] = run; run += tmp; }
    }
    __syncthreads();
    if (i < N_NODES) {
        int pre = ws[wid] + (v - d) + g_bpre[b];
        g_off[i] = pre;
        g_cur[i] = pre;
        g_dis[i] = rsqrtf((float)d + 1.0f);
        if (i == N_NODES - 1) g_off[N_NODES] = pre + d;
    }
}

// ---------------- CSR fill (counting sort by col) ---------------------------
__global__ void k_fill(const int* __restrict__ row, const int* __restrict__ col) {
    int e = blockIdx.x * blockDim.x + threadIdx.x;
    if (e >= N_EDGES) return;
    int pos = atomicAdd(&g_cur[col[e]], 1);
    g_csr[pos] = row[e];
}

// ---------------- GEMM: Y[M,N] = (X[M,128] @ W[128,N]) * dis[row] -----------
// 512 threads, tile 128 rows. Per thread: 4 rows x (N==128 ? 8 : 4) cols.
template <int N>
__global__ __launch_bounds__(512) void k_gemm(const float* __restrict__ X,
                                              const float* __restrict__ W,
                                              float* __restrict__ Y) {
    constexpr int TILE_M = 128;
    constexpr int LDX = 132;
    constexpr int TN = (N == 128) ? 8 : 4;
    extern __shared__ float smem[];
    float* sW = smem;                 // 128 * N
    float* sX = smem + 128 * N;       // 128 * 132

    const int tid = threadIdx.x;
    const int m0  = blockIdx.x * TILE_M;

    {   // stage W
        const float4* W4 = (const float4*)W;
        float4* sW4 = (float4*)sW;
        #pragma unroll
        for (int i = tid; i < 128 * N / 4; i += 512) sW4[i] = W4[i];
    }
    {   // stage X tile
        #pragma unroll
        for (int i = tid; i < TILE_M * 32; i += 512) {
            int rr = i >> 5, kk = i & 31;
            int gr = m0 + rr;
            float4 v = (gr < N_NODES) ? ((const float4*)X)[gr * 32 + kk]
                                      : make_float4(0.f, 0.f, 0.f, 0.f);
            *(float4*)(sX + rr * LDX + kk * 4) = v;
        }
    }
    __syncthreads();

    const int tn = tid & 15;
    const int tm = tid >> 4;   // 0..31, 4 rows each

    float acc[4][TN];
    #pragma unroll
    for (int i = 0; i < 4; i++)
        #pragma unroll
        for (int j = 0; j < TN; j++) acc[i][j] = 0.f;

    const float4* sW4 = (const float4*)sW;
    const float*  xb  = sX + tm * 4 * LDX;

    #pragma unroll 4
    for (int k = 0; k < 128; k++) {
        float a[4];
        #pragma unroll
        for (int i = 0; i < 4; i++) a[i] = xb[i * LDX + k];
        if constexpr (N == 128) {
            float4 b0 = sW4[k * 32 + tn];
            float4 b1 = sW4[k * 32 + tn + 16];
            #pragma unroll
            for (int i = 0; i < 4; i++) {
                acc[i][0] = fmaf(a[i], b0.x, acc[i][0]);
                acc[i][1] = fmaf(a[i], b0.y, acc[i][1]);
                acc[i][2] = fmaf(a[i], b0.z, acc[i][2]);
                acc[i][3] = fmaf(a[i], b0.w, acc[i][3]);
                acc[i][4] = fmaf(a[i], b1.x, acc[i][4]);
                acc[i][5] = fmaf(a[i], b1.y, acc[i][5]);
                acc[i][6] = fmaf(a[i], b1.z, acc[i][6]);
                acc[i][7] = fmaf(a[i], b1.w, acc[i][7]);
            }
        } else {
            float4 b0 = sW4[k * 16 + tn];
            #pragma unroll
            for (int i = 0; i < 4; i++) {
                acc[i][0] = fmaf(a[i], b0.x, acc[i][0]);
                acc[i][1] = fmaf(a[i], b0.y, acc[i][1]);
                acc[i][2] = fmaf(a[i], b0.z, acc[i][2]);
                acc[i][3] = fmaf(a[i], b0.w, acc[i][3]);
            }
        }
    }

    #pragma unroll
    for (int i = 0; i < 4; i++) {
        int gr = m0 + tm * 4 + i;
        if (gr < N_NODES) {
            float s = g_dis[gr];
            *(float4*)(Y + gr * N + tn * 4) =
                make_float4(acc[i][0] * s, acc[i][1] * s, acc[i][2] * s, acc[i][3] * s);
            if constexpr (N == 128)
                *(float4*)(Y + gr * N + 64 + tn * 4) =
                    make_float4(acc[i][4] * s, acc[i][5] * s, acc[i][6] * s, acc[i][7] * s);
        }
    }
}

// ---------------- layer-1 aggregation: warp per node, 128 ch ----------------
// h1 = relu( dis_i * (sum_e hs[row_e] + hs[i]) + b1 )
__global__ void k_agg1(const float* __restrict__ b1) {
    int w = (blockIdx.x * blockDim.x + threadIdx.x) >> 5;
    if (w >= N_NODES) return;
    int lane = threadIdx.x & 31;
    int beg = g_off[w], end = g_off[w + 1];
    const float4* h4 = (const float4*)g_h;
    float4 acc = make_float4(0.f, 0.f, 0.f, 0.f);

    for (int base = beg; base < end; base += 32) {
        int n = end - base; if (n > 32) n = 32;
        int ed = (base + lane < end) ? g_csr[base + lane] : 0;
        int j = 0;
        for (; j + 4 <= n; j += 4) {
            int r0 = __shfl_sync(0xffffffffu, ed, j);
            int r1 = __shfl_sync(0xffffffffu, ed, j + 1);
            int r2 = __shfl_sync(0xffffffffu, ed, j + 2);
            int r3 = __shfl_sync(0xffffffffu, ed, j + 3);
            float4 v0 = h4[r0 * 32 + lane];
            float4 v1 = h4[r1 * 32 + lane];
            float4 v2 = h4[r2 * 32 + lane];
            float4 v3 = h4[r3 * 32 + lane];
            acc.x += (v0.x + v1.x) + (v2.x + v3.x);
            acc.y += (v0.y + v1.y) + (v2.y + v3.y);
            acc.z += (v0.z + v1.z) + (v2.z + v3.z);
            acc.w += (v0.w + v1.w) + (v2.w + v3.w);
        }
        for (; j < n; j++) {
            int r0 = __shfl_sync(0xffffffffu, ed, j);
            float4 v0 = h4[r0 * 32 + lane];
            acc.x += v0.x; acc.y += v0.y; acc.z += v0.z; acc.w += v0.w;
        }
    }
    float di = g_dis[w];
    float4 hs = h4[w * 32 + lane];
    float4 bb = ((const float4*)b1)[lane];
    float4 o;
    o.x = fmaxf(fmaf(acc.x + hs.x, di, bb.x), 0.f);
    o.y = fmaxf(fmaf(acc.y + hs.y, di, bb.y), 0.f);
    o.z = fmaxf(fmaf(acc.z + hs.z, di, bb.z), 0.f);
    o.w = fmaxf(fmaf(acc.w + hs.w, di, bb.w), 0.f);
    ((float4*)g_h1)[w * 32 + lane] = o;
}

// ---------------- layer-2 aggregation: warp per node, 64 ch -----------------
__global__ void k_agg2(const float* __restrict__ b2) {
    int w = (blockIdx.x * blockDim.x + threadIdx.x) >> 5;
    if (w >= N_NODES) return;
    int lane = threadIdx.x & 31;
    int beg = g_off[w], end = g_off[w + 1];
    const float2* z2 = (const float2*)g_z;
    float2 acc = make_float2(0.f, 0.f);

    for (int base = beg; base < end; base += 32) {
        int n = end - base; if (n > 32) n = 32;
        int ed = (base + lane < end) ? g_csr[base + lane] : 0;
        int j = 0;
        for (; j + 4 <= n; j += 4) {
            int r0 = __shfl_sync(0xffffffffu, ed, j);
            int r1 = __shfl_sync(0xffffffffu, ed, j + 1);
            int r2 = __shfl_sync(0xffffffffu, ed, j + 2);
            int r3 = __shfl_sync(0xffffffffu, ed, j + 3);
            float2 v0 = z2[r0 * 32 + lane];
            float2 v1 = z2[r1 * 32 + lane];
            float2 v2 = z2[r2 * 32 + lane];
            float2 v3 = z2[r3 * 32 + lane];
            acc.x += (v0.x + v1.x) + (v2.x + v3.x);
            acc.y += (v0.y + v1.y) + (v2.y + v3.y);
        }
        for (; j < n; j++) {
            int r0 = __shfl_sync(0xffffffffu, ed, j);
            float2 v0 = z2[r0 * 32 + lane];
            acc.x += v0.x; acc.y += v0.y;
        }
    }
    float di = g_dis[w];
    float2 zs = z2[w * 32 + lane];
    float2 bb = ((const float2*)b2)[lane];
    float2 o;
    o.x = fmaf(acc.x + zs.x, di, bb.x);
    o.y = fmaf(acc.y + zs.y, di, bb.y);
    ((float2*)g_zf)[w * 32 + lane] = o;
}

// ---------------- decode: 16-lane group per label edge ----------------------
__global__ void k_decode(const int* __restrict__ src, const int* __restrict__ dst,
                         float* __restrict__ out) {
    int t = blockIdx.x * blockDim.x + threadIdx.x;
    int e = t >> 4;
    if (e >= N_LABEL) return;
    int sub = t & 15;
    int s = __ldg(src + e);
    int d = __ldg(dst + e);
    const float4* z4 = (const float4*)g_zf;
    float4 a = z4[s * 16 + sub];
    float4 b = z4[d * 16 + sub];
    float p = a.x * b.x + a.y * b.y + a.z * b.z + a.w * b.w;
    p += __shfl_xor_sync(0xffffffffu, p, 8, 16);
    p += __shfl_xor_sync(0xffffffffu, p, 4, 16);
    p += __shfl_xor_sync(0xffffffffu, p, 2, 16);
    p += __shfl_xor_sync(0xffffffffu, p, 1, 16);
    if (sub == 0) out[e] = p;
}

// ---------------- launch ----------------------------------------------------
extern "C" void kernel_launch(void* const* d_in, const int* in_sizes, int n_in,
                              void* d_out, int out_size) {
    const float* x  = (const float*)d_in[0];
    const float* W1 = (const float*)d_in[1];
    const float* b1 = (const float*)d_in[2];
    const float* W2 = (const float*)d_in[3];
    const float* b2 = (const float*)d_in[4];
    const int* edge_index = (const int*)d_in[5];
    const int* edge_label = (const int*)d_in[6];
    float* out = (float*)d_out;

    const int* erow = edge_index;
    const int* ecol = edge_index + N_EDGES;
    const int* lsrc = edge_label;
    const int* ldst = edge_label + N_LABEL;

    float *ph, *ph1, *pz;
    cudaGetSymbolAddress((void**)&ph,  g_h);
    cudaGetSymbolAddress((void**)&ph1, g_h1);
    cudaGetSymbolAddress((void**)&pz,  g_z);

    const int smem128 = (128 * 128 + 128 * 132) * sizeof(float);  // 133120
    const int smem64  = (128 * 64  + 128 * 132) * sizeof(float);  // 100352
    cudaFuncSetAttribute(k_gemm<128>, cudaFuncAttributeMaxDynamicSharedMemorySize, smem128);
    cudaFuncSetAttribute(k_gemm<64>,  cudaFuncAttributeMaxDynamicSharedMemorySize, smem64);

    // CSR build
    k_zero<<<(N_NODES + 255) / 256, 256>>>();
    k_deg<<<(N_EDGES + 255) / 256, 256>>>(ecol);
    k_scanA<<<NBLK, 256>>>();
    k_scanB<<<1, 256>>>();
    k_scanC<<<NBLK, 256>>>();
    k_fill<<<(N_EDGES + 255) / 256, 256>>>(erow, ecol);
    // layer 1
    k_gemm<128><<<(N_NODES + 127) / 128, 512, smem128>>>(x, W1, ph);
    k_agg1<<<(N_NODES * 32 + 255) / 256, 256>>>(b1);
    // layer 2
    k_gemm<64><<<(N_NODES + 127) / 128, 512, smem64>>>(ph1, W2, pz);
    k_agg2<<<(N_NODES * 32 + 255) / 256, 256>>>(b2);
    // decode
    k_decode<<<(N_LABEL * 16 + 255) / 256, 256>>>(lsrc, ldst, out);
}

// round 6
// speedup vs baseline: 2.0929x; 1.0446x over previous
#include <cuda_runtime.h>

#define N_NODES 50000
#define N_EDGES 800000
#define N_LABEL 200000
#define NBLK 196           // ceil(50000/256)
#define GEMM_TILES 391     // ceil(50000/128)
#define DEG_BLOCKS 48

// ---------------- scratch (device globals; no allocation allowed) ----------
__device__ int   g_degi[N_NODES];
__device__ int   g_off[N_NODES + 1];
__device__ int   g_cur[N_NODES];
__device__ float g_dis[N_NODES];     // (deg+1)^-1/2
__device__ int   g_bsum[256];
__device__ __align__(16) int   g_csr[N_EDGES];        // src row only
__device__ __align__(16) float g_h [N_NODES * 128];   // x @ W1 (UNSCALED)
__device__ __align__(16) float g_h1[N_NODES * 128];   // relu layer-1 output
__device__ __align__(16) float g_z [N_NODES * 64];    // (h1 @ W2) * dis[row]
__device__ __align__(16) float g_zf[N_NODES * 64];    // final embeddings

// ---------------- scan stage A: per-block sums -------------------------------
__global__ void k_scanA() {
    int t = threadIdx.x, b = blockIdx.x;
    int i = b * 256 + t;
    int d = (i < N_NODES) ? g_degi[i] : 0;
    int v = d;
    #pragma unroll
    for (int o = 16; o; o >>= 1) v += __shfl_xor_sync(0xffffffffu, v, o);
    __shared__ int ws[8];
    if ((t & 31) == 0) ws[t >> 5] = v;
    __syncthreads();
    if (t == 0) {
        int s = 0;
        #pragma unroll
        for (int k = 0; k < 8; k++) s += ws[k];
        g_bsum[b] = s;
    }
}

// ---------------- scan stage C: offsets + norm (re-scans bsum locally) -------
__global__ void k_scanC() {
    int t = threadIdx.x, b = blockIdx.x;
    int lane = t & 31, wid = t >> 5;
    __shared__ int ws[8];
    __shared__ int sb[256];

    // 1) exclusive scan of the 196 block sums (all blocks redo it; cheap)
    {
        int d = (t < NBLK) ? g_bsum[t] : 0;
        int v = d;
        #pragma unroll
        for (int o = 1; o < 32; o <<= 1) {
            int u = __shfl_up_sync(0xffffffffu, v, o);
            if (lane >= o) v += u;
        }
        if (lane == 31) ws[wid] = v;
        __syncthreads();
        if (t == 0) {
            int run = 0;
            #pragma unroll
            for (int k = 0; k < 8; k++) { int tmp = ws[k]; ws[k] = run; run += tmp; }
        }
        __syncthreads();
        sb[t] = ws[wid] + v - d;   // exclusive prefix of bsum
        __syncthreads();
    }
    int bpre = sb[b];

    // 2) local scan of this block's 256 degrees
    int i = b * 256 + t;
    int d = (i < N_NODES) ? g_degi[i] : 0;
    int v = d;
    #pragma unroll
    for (int o = 1; o < 32; o <<= 1) {
        int u = __shfl_up_sync(0xffffffffu, v, o);
        if (lane >= o) v += u;
    }
    __syncthreads();
    if (lane == 31) ws[wid] = v;
    __syncthreads();
    if (t == 0) {
        int run = 0;
        #pragma unroll
        for (int k = 0; k < 8; k++) { int tmp = ws[k]; ws[k] = run; run += tmp; }
    }
    __syncthreads();
    if (i < N_NODES) {
        int pre = ws[wid] + (v - d) + bpre;
        g_off[i] = pre;
        g_cur[i] = pre;
        g_dis[i] = rsqrtf((float)d + 1.0f);
        if (i == N_NODES - 1) g_off[N_NODES] = pre + d;
    }
}

// ---------------- CSR fill (counting sort by col) ---------------------------
__global__ void k_fill(const int* __restrict__ row, const int* __restrict__ col) {
    int e = blockIdx.x * blockDim.x + threadIdx.x;
    if (e >= N_EDGES) return;
    int pos = atomicAdd(&g_cur[col[e]], 1);
    g_csr[pos] = row[e];
}

// ---------------- GEMM: Y = X @ W; N==128 fuses degree count, no scaling ----
// N==64 scales by dis[row] in the epilogue (dis ready by then).
template <int N>
__global__ __launch_bounds__(512) void k_gemm(const float* __restrict__ X,
                                              const float* __restrict__ W,
                                              float* __restrict__ Y,
                                              const int* __restrict__ col) {
    const int tid = threadIdx.x;

    if constexpr (N == 128) {
        if (blockIdx.x >= GEMM_TILES) {
            // degree-count blocks (piggyback on the gemm's tail wave)
            int b = blockIdx.x - GEMM_TILES;
            for (int e = b * 512 + tid; e < N_EDGES; e += DEG_BLOCKS * 512)
                atomicAdd(&g_degi[col[e]], 1);
            return;
        }
    }

    constexpr int TILE_M = 128;
    constexpr int LDX = 132;
    constexpr int TN = (N == 128) ? 8 : 4;
    extern __shared__ float smem[];
    float* sW = smem;                 // 128 * N
    float* sX = smem + 128 * N;       // 128 * 132

    const int m0 = blockIdx.x * TILE_M;

    {   // stage W
        const float4* W4 = (const float4*)W;
        float4* sW4 = (float4*)sW;
        #pragma unroll
        for (int i = tid; i < 128 * N / 4; i += 512) sW4[i] = W4[i];
    }
    {   // stage X tile
        #pragma unroll
        for (int i = tid; i < TILE_M * 32; i += 512) {
            int rr = i >> 5, kk = i & 31;
            int gr = m0 + rr;
            float4 v = (gr < N_NODES) ? ((const float4*)X)[gr * 32 + kk]
                                      : make_float4(0.f, 0.f, 0.f, 0.f);
            *(float4*)(sX + rr * LDX + kk * 4) = v;
        }
    }
    __syncthreads();

    const int tn = tid & 15;
    const int tm = tid >> 4;   // 0..31, 4 rows each

    float acc[4][TN];
    #pragma unroll
    for (int i = 0; i < 4; i++)
        #pragma unroll
        for (int j = 0; j < TN; j++) acc[i][j] = 0.f;

    const float4* sW4 = (const float4*)sW;
    const float*  xb  = sX + tm * 4 * LDX;

    #pragma unroll 4
    for (int k = 0; k < 128; k++) {
        float a[4];
        #pragma unroll
        for (int i = 0; i < 4; i++) a[i] = xb[i * LDX + k];
        if constexpr (N == 128) {
            float4 b0 = sW4[k * 32 + tn];
            float4 b1 = sW4[k * 32 + tn + 16];
            #pragma unroll
            for (int i = 0; i < 4; i++) {
                acc[i][0] = fmaf(a[i], b0.x, acc[i][0]);
                acc[i][1] = fmaf(a[i], b0.y, acc[i][1]);
                acc[i][2] = fmaf(a[i], b0.z, acc[i][2]);
                acc[i][3] = fmaf(a[i], b0.w, acc[i][3]);
                acc[i][4] = fmaf(a[i], b1.x, acc[i][4]);
                acc[i][5] = fmaf(a[i], b1.y, acc[i][5]);
                acc[i][6] = fmaf(a[i], b1.z, acc[i][6]);
                acc[i][7] = fmaf(a[i], b1.w, acc[i][7]);
            }
        } else {
            float4 b0 = sW4[k * 16 + tn];
            #pragma unroll
            for (int i = 0; i < 4; i++) {
                acc[i][0] = fmaf(a[i], b0.x, acc[i][0]);
                acc[i][1] = fmaf(a[i], b0.y, acc[i][1]);
                acc[i][2] = fmaf(a[i], b0.z, acc[i][2]);
                acc[i][3] = fmaf(a[i], b0.w, acc[i][3]);
            }
        }
    }

    #pragma unroll
    for (int i = 0; i < 4; i++) {
        int gr = m0 + tm * 4 + i;
        if (gr < N_NODES) {
            if constexpr (N == 128) {
                // UNSCALED (g_dis not ready yet; agg1 applies per-edge scale)
                *(float4*)(Y + gr * N + tn * 4) =
                    make_float4(acc[i][0], acc[i][1], acc[i][2], acc[i][3]);
                *(float4*)(Y + gr * N + 64 + tn * 4) =
                    make_float4(acc[i][4], acc[i][5], acc[i][6], acc[i][7]);
            } else {
                float s = g_dis[gr];
                *(float4*)(Y + gr * N + tn * 4) =
                    make_float4(acc[i][0] * s, acc[i][1] * s, acc[i][2] * s, acc[i][3] * s);
            }
        }
    }
}

// ---------------- layer-1 aggregation: warp per node, 128 ch ----------------
// h1 = relu( dis_i * (sum_e dis_re*h[row_e] + dis_i*h[i]) + b1 )
__global__ void k_agg1(const float* __restrict__ b1) {
    int w = (blockIdx.x * blockDim.x + threadIdx.x) >> 5;
    if (w >= N_NODES) return;
    int lane = threadIdx.x & 31;
    int beg = g_off[w], end = g_off[w + 1];
    const float4* h4 = (const float4*)g_h;
    float4 acc = make_float4(0.f, 0.f, 0.f, 0.f);

    for (int base = beg; base < end; base += 32) {
        int n = end - base; if (n > 32) n = 32;
        int ed = 0; float ds = 0.f;
        if (base + lane < end) {
            ed = g_csr[base + lane];
            ds = g_dis[ed];
        }
        int dsb = __float_as_int(ds);
        int j = 0;
        for (; j + 8 <= n; j += 8) {
            int r[8]; float m[8]; float4 v[8];
            #pragma unroll
            for (int u = 0; u < 8; u++) {
                r[u] = __shfl_sync(0xffffffffu, ed, j + u);
                m[u] = __int_as_float(__shfl_sync(0xffffffffu, dsb, j + u));
            }
            #pragma unroll
            for (int u = 0; u < 8; u++) v[u] = h4[r[u] * 32 + lane];
            #pragma unroll
            for (int u = 0; u < 8; u++) {
                acc.x = fmaf(v[u].x, m[u], acc.x);
                acc.y = fmaf(v[u].y, m[u], acc.y);
                acc.z = fmaf(v[u].z, m[u], acc.z);
                acc.w = fmaf(v[u].w, m[u], acc.w);
            }
        }
        if (j + 4 <= n) {
            int r[4]; float m[4]; float4 v[4];
            #pragma unroll
            for (int u = 0; u < 4; u++) {
                r[u] = __shfl_sync(0xffffffffu, ed, j + u);
                m[u] = __int_as_float(__shfl_sync(0xffffffffu, dsb, j + u));
            }
            #pragma unroll
            for (int u = 0; u < 4; u++) v[u] = h4[r[u] * 32 + lane];
            #pragma unroll
            for (int u = 0; u < 4; u++) {
                acc.x = fmaf(v[u].x, m[u], acc.x);
                acc.y = fmaf(v[u].y, m[u], acc.y);
                acc.z = fmaf(v[u].z, m[u], acc.z);
                acc.w = fmaf(v[u].w, m[u], acc.w);
            }
            j += 4;
        }
        for (; j < n; j++) {
            int   r0 = __shfl_sync(0xffffffffu, ed, j);
            float m0 = __int_as_float(__shfl_sync(0xffffffffu, dsb, j));
            float4 v0 = h4[r0 * 32 + lane];
            acc.x = fmaf(v0.x, m0, acc.x);
            acc.y = fmaf(v0.y, m0, acc.y);
            acc.z = fmaf(v0.z, m0, acc.z);
            acc.w = fmaf(v0.w, m0, acc.w);
        }
    }
    float di = g_dis[w];
    float4 hs = h4[w * 32 + lane];      // unscaled h_i
    float4 bb = ((const float4*)b1)[lane];
    // acc += dis_i * h_i ; out = relu(dis_i * acc + b)
    acc.x = fmaf(hs.x, di, acc.x);
    acc.y = fmaf(hs.y, di, acc.y);
    acc.z = fmaf(hs.z, di, acc.z);
    acc.w = fmaf(hs.w, di, acc.w);
    float4 o;
    o.x = fmaxf(fmaf(acc.x, di, bb.x), 0.f);
    o.y = fmaxf(fmaf(acc.y, di, bb.y), 0.f);
    o.z = fmaxf(fmaf(acc.z, di, bb.z), 0.f);
    o.w = fmaxf(fmaf(acc.w, di, bb.w), 0.f);
    ((float4*)g_h1)[w * 32 + lane] = o;
}

// ---------------- layer-2 aggregation: warp per node, 64 ch -----------------
// z is pre-scaled by dis[row] (gemm64 epilogue), so pure adds here.
__global__ void k_agg2(const float* __restrict__ b2) {
    int w = (blockIdx.x * blockDim.x + threadIdx.x) >> 5;
    if (w >= N_NODES) return;
    int lane = threadIdx.x & 31;
    int beg = g_off[w], end = g_off[w + 1];
    const float2* z2 = (const float2*)g_z;
    float2 acc = make_float2(0.f, 0.f);

    for (int base = beg; base < end; base += 32) {
        int n = end - base; if (n > 32) n = 32;
        int ed = (base + lane < end) ? g_csr[base + lane] : 0;
        int j = 0;
        for (; j + 8 <= n; j += 8) {
            int r[8]; float2 v[8];
            #pragma unroll
            for (int u = 0; u < 8; u++) r[u] = __shfl_sync(0xffffffffu, ed, j + u);
            #pragma unroll
            for (int u = 0; u < 8; u++) v[u] = z2[r[u] * 32 + lane];
            acc.x += ((v[0].x + v[1].x) + (v[2].x + v[3].x)) + ((v[4].x + v[5].x) + (v[6].x + v[7].x));
            acc.y += ((v[0].y + v[1].y) + (v[2].y + v[3].y)) + ((v[4].y + v[5].y) + (v[6].y + v[7].y));
        }
        if (j + 4 <= n) {
            int r[4]; float2 v[4];
            #pragma unroll
            for (int u = 0; u < 4; u++) r[u] = __shfl_sync(0xffffffffu, ed, j + u);
            #pragma unroll
            for (int u = 0; u < 4; u++) v[u] = z2[r[u] * 32 + lane];
            acc.x += (v[0].x + v[1].x) + (v[2].x + v[3].x);
            acc.y += (v[0].y + v[1].y) + (v[2].y + v[3].y);
            j += 4;
        }
        for (; j < n; j++) {
            int r0 = __shfl_sync(0xffffffffu, ed, j);
            float2 v0 = z2[r0 * 32 + lane];
            acc.x += v0.x; acc.y += v0.y;
        }
    }
    float di = g_dis[w];
    float2 zs = z2[w * 32 + lane];
    float2 bb = ((const float2*)b2)[lane];
    float2 o;
    o.x = fmaf(acc.x + zs.x, di, bb.x);
    o.y = fmaf(acc.y + zs.y, di, bb.y);
    ((float2*)g_zf)[w * 32 + lane] = o;
}

// ---------------- decode: 16-lane group per label edge ----------------------
__global__ void k_decode(const int* __restrict__ src, const int* __restrict__ dst,
                         float* __restrict__ out) {
    int t = blockIdx.x * blockDim.x + threadIdx.x;
    int e = t >> 4;
    if (e >= N_LABEL) return;
    int sub = t & 15;
    int s = __ldg(src + e);
    int d = __ldg(dst + e);
    const float4* z4 = (const float4*)g_zf;
    float4 a = z4[s * 16 + sub];
    float4 b = z4[d * 16 + sub];
    float p = a.x * b.x + a.y * b.y + a.z * b.z + a.w * b.w;
    p += __shfl_xor_sync(0xffffffffu, p, 8, 16);
    p += __shfl_xor_sync(0xffffffffu, p, 4, 16);
    p += __shfl_xor_sync(0xffffffffu, p, 2, 16);
    p += __shfl_xor_sync(0xffffffffu, p, 1, 16);
    if (sub == 0) out[e] = p;
}

// ---------------- launch ----------------------------------------------------
extern "C" void kernel_launch(void* const* d_in, const int* in_sizes, int n_in,
                              void* d_out, int out_size) {
    const float* x  = (const float*)d_in[0];
    const float* W1 = (const float*)d_in[1];
    const float* b1 = (const float*)d_in[2];
    const float* W2 = (const float*)d_in[3];
    const float* b2 = (const float*)d_in[4];
    const int* edge_index = (const int*)d_in[5];
    const int* edge_label = (const int*)d_in[6];
    float* out = (float*)d_out;

    const int* erow = edge_index;
    const int* ecol = edge_index + N_EDGES;
    const int* lsrc = edge_label;
    const int* ldst = edge_label + N_LABEL;

    float *ph, *ph1, *pz;
    int   *pdeg;
    cudaGetSymbolAddress((void**)&ph,   g_h);
    cudaGetSymbolAddress((void**)&ph1,  g_h1);
    cudaGetSymbolAddress((void**)&pz,   g_z);
    cudaGetSymbolAddress((void**)&pdeg, g_degi);

    const int smem128 = (128 * 128 + 128 * 132) * sizeof(float);  // 133120
    const int smem64  = (128 * 64  + 128 * 132) * sizeof(float);  // 100352
    cudaFuncSetAttribute(k_gemm<128>, cudaFuncAttributeMaxDynamicSharedMemorySize, smem128);
    cudaFuncSetAttribute(k_gemm<64>,  cudaFuncAttributeMaxDynamicSharedMemorySize, smem64);

    // zero degrees (async memset, graph-capturable)
    cudaMemsetAsync(pdeg, 0, N_NODES * sizeof(int), 0);
    // gemm layer 1 (unscaled) + fused degree count in tail-wave blocks
    k_gemm<128><<<GEMM_TILES + DEG_BLOCKS, 512, smem128>>>(x, W1, ph, ecol);
    // offsets + norm factors
    k_scanA<<<NBLK, 256>>>();
    k_scanC<<<NBLK, 256>>>();
    // CSR fill
    k_fill<<<(N_EDGES + 255) / 256, 256>>>(erow, ecol);
    // layer-1 aggregation (applies per-edge dis[row] and final dis_i)
    k_agg1<<<(N_NODES * 32 + 255) / 256, 256>>>(b1);
    // layer 2
    k_gemm<64><<<GEMM_TILES, 512, smem64>>>(ph1, W2, pz, nullptr);
    k_agg2<<<(N_NODES * 32 + 255) / 256, 256>>>(b2);
    // decode
    k_decode<<<(N_LABEL * 16 + 255) / 256, 256>>>(lsrc, ldst, out);
}

// round 7
// speedup vs baseline: 2.1879x; 1.0454x over previous
#include <cuda_runtime.h>

#define N_NODES 50000
#define N_EDGES 800000
#define N_LABEL 200000
#define NBLK 196           // ceil(50000/256)
#define GEMM_TILES 391     // ceil(50000/128)

// ---------------- scratch (device globals; no allocation allowed) ----------
__device__ int   g_degi[N_NODES];
__device__ int   g_off[N_NODES + 1];
__device__ int   g_cur[N_NODES];
__device__ float g_dis[N_NODES];     // (deg+1)^-1/2
__device__ int   g_bsum[256];
__device__ __align__(16) int   g_csr[N_EDGES];        // src row only
__device__ __align__(16) float g_h [N_NODES * 128];   // x @ W1 (UNSCALED)
__device__ __align__(16) float g_h1[N_NODES * 128];   // relu layer-1 output
__device__ __align__(16) float g_z [N_NODES * 64];    // (h1 @ W2) * dis[row]
__device__ __align__(16) float g_zf[N_NODES * 64];    // final embeddings

// ---------------- side stream + events (created once at load time) ---------
static cudaStream_t g_s2 = 0;
static cudaEvent_t  g_evA = 0, g_evB = 0;
namespace {
struct StreamInit {
    StreamInit() {
        if (cudaStreamCreateWithFlags(&g_s2, cudaStreamNonBlocking) != cudaSuccess) { g_s2 = 0; return; }
        if (cudaEventCreateWithFlags(&g_evA, cudaEventDisableTiming) != cudaSuccess) { g_s2 = 0; return; }
        if (cudaEventCreateWithFlags(&g_evB, cudaEventDisableTiming) != cudaSuccess) { g_s2 = 0; return; }
    }
};
static StreamInit s_init;
}

// ---------------- degree (4 edges/thread) -----------------------------------
__global__ void k_deg(const int4* __restrict__ col4) {
    int i = blockIdx.x * blockDim.x + threadIdx.x;
    if (i < N_EDGES / 4) {
        int4 c = col4[i];
        atomicAdd(&g_degi[c.x], 1);
        atomicAdd(&g_degi[c.y], 1);
        atomicAdd(&g_degi[c.z], 1);
        atomicAdd(&g_degi[c.w], 1);
    }
}

// ---------------- scan stage A: per-block sums -------------------------------
__global__ void k_scanA() {
    int t = threadIdx.x, b = blockIdx.x;
    int i = b * 256 + t;
    int d = (i < N_NODES) ? g_degi[i] : 0;
    int v = d;
    #pragma unroll
    for (int o = 16; o; o >>= 1) v += __shfl_xor_sync(0xffffffffu, v, o);
    __shared__ int ws[8];
    if ((t & 31) == 0) ws[t >> 5] = v;
    __syncthreads();
    if (t == 0) {
        int s = 0;
        #pragma unroll
        for (int k = 0; k < 8; k++) s += ws[k];
        g_bsum[b] = s;
    }
}

// ---------------- scan stage C: offsets + norm (re-scans bsum locally) -------
__global__ void k_scanC() {
    int t = threadIdx.x, b = blockIdx.x;
    int lane = t & 31, wid = t >> 5;
    __shared__ int ws[8];
    __shared__ int sb[256];

    {   // exclusive scan of the 196 block sums (every block redoes it; cheap)
        int d = (t < NBLK) ? g_bsum[t] : 0;
        int v = d;
        #pragma unroll
        for (int o = 1; o < 32; o <<= 1) {
            int u = __shfl_up_sync(0xffffffffu, v, o);
            if (lane >= o) v += u;
        }
        if (lane == 31) ws[wid] = v;
        __syncthreads();
        if (t == 0) {
            int run = 0;
            #pragma unroll
            for (int k = 0; k < 8; k++) { int tmp = ws[k]; ws[k] = run; run += tmp; }
        }
        __syncthreads();
        sb[t] = ws[wid] + v - d;
        __syncthreads();
    }
    int bpre = sb[b];

    int i = b * 256 + t;
    int d = (i < N_NODES) ? g_degi[i] : 0;
    int v = d;
    #pragma unroll
    for (int o = 1; o < 32; o <<= 1) {
        int u = __shfl_up_sync(0xffffffffu, v, o);
        if (lane >= o) v += u;
    }
    __syncthreads();
    if (lane == 31) ws[wid] = v;
    __syncthreads();
    if (t == 0) {
        int run = 0;
        #pragma unroll
        for (int k = 0; k < 8; k++) { int tmp = ws[k]; ws[k] = run; run += tmp; }
    }
    __syncthreads();
    if (i < N_NODES) {
        int pre = ws[wid] + (v - d) + bpre;
        g_off[i] = pre;
        g_cur[i] = pre;
        g_dis[i] = rsqrtf((float)d + 1.0f);
        if (i == N_NODES - 1) g_off[N_NODES] = pre + d;
    }
}

// ---------------- CSR fill (counting sort by col, 4 edges/thread) -----------
__global__ void k_fill(const int4* __restrict__ row4, const int4* __restrict__ col4) {
    int i = blockIdx.x * blockDim.x + threadIdx.x;
    if (i >= N_EDGES / 4) return;
    int4 r = row4[i];
    int4 c = col4[i];
    int p0 = atomicAdd(&g_cur[c.x], 1);
    int p1 = atomicAdd(&g_cur[c.y], 1);
    int p2 = atomicAdd(&g_cur[c.z], 1);
    int p3 = atomicAdd(&g_cur[c.w], 1);
    g_csr[p0] = r.x;
    g_csr[p1] = r.y;
    g_csr[p2] = r.z;
    g_csr[p3] = r.w;
}

// ---------------- GEMM: Y = X @ W (N==128 unscaled; N==64 scaled) -----------
template <int N>
__global__ __launch_bounds__(512) void k_gemm(const float* __restrict__ X,
                                              const float* __restrict__ W,
                                              float* __restrict__ Y) {
    constexpr int TILE_M = 128;
    constexpr int LDX = 132;
    constexpr int TN = (N == 128) ? 8 : 4;
    extern __shared__ float smem[];
    float* sW = smem;                 // 128 * N
    float* sX = smem + 128 * N;       // 128 * 132

    const int tid = threadIdx.x;
    const int m0 = blockIdx.x * TILE_M;

    {   // stage W
        const float4* W4 = (const float4*)W;
        float4* sW4 = (float4*)sW;
        #pragma unroll
        for (int i = tid; i < 128 * N / 4; i += 512) sW4[i] = W4[i];
    }
    {   // stage X tile
        #pragma unroll
        for (int i = tid; i < TILE_M * 32; i += 512) {
            int rr = i >> 5, kk = i & 31;
            int gr = m0 + rr;
            float4 v = (gr < N_NODES) ? ((const float4*)X)[gr * 32 + kk]
                                      : make_float4(0.f, 0.f, 0.f, 0.f);
            *(float4*)(sX + rr * LDX + kk * 4) = v;
        }
    }
    __syncthreads();

    const int tn = tid & 15;
    const int tm = tid >> 4;   // 0..31, 4 rows each

    float acc[4][TN];
    #pragma unroll
    for (int i = 0; i < 4; i++)
        #pragma unroll
        for (int j = 0; j < TN; j++) acc[i][j] = 0.f;

    const float4* sW4 = (const float4*)sW;
    const float*  xb  = sX + tm * 4 * LDX;

    #pragma unroll 4
    for (int k = 0; k < 128; k++) {
        float a[4];
        #pragma unroll
        for (int i = 0; i < 4; i++) a[i] = xb[i * LDX + k];
        if constexpr (N == 128) {
            float4 b0 = sW4[k * 32 + tn];
            float4 b1 = sW4[k * 32 + tn + 16];
            #pragma unroll
            for (int i = 0; i < 4; i++) {
                acc[i][0] = fmaf(a[i], b0.x, acc[i][0]);
                acc[i][1] = fmaf(a[i], b0.y, acc[i][1]);
                acc[i][2] = fmaf(a[i], b0.z, acc[i][2]);
                acc[i][3] = fmaf(a[i], b0.w, acc[i][3]);
                acc[i][4] = fmaf(a[i], b1.x, acc[i][4]);
                acc[i][5] = fmaf(a[i], b1.y, acc[i][5]);
                acc[i][6] = fmaf(a[i], b1.z, acc[i][6]);
                acc[i][7] = fmaf(a[i], b1.w, acc[i][7]);
            }
        } else {
            float4 b0 = sW4[k * 16 + tn];
            #pragma unroll
            for (int i = 0; i < 4; i++) {
                acc[i][0] = fmaf(a[i], b0.x, acc[i][0]);
                acc[i][1] = fmaf(a[i], b0.y, acc[i][1]);
                acc[i][2] = fmaf(a[i], b0.z, acc[i][2]);
                acc[i][3] = fmaf(a[i], b0.w, acc[i][3]);
            }
        }
    }

    #pragma unroll
    for (int i = 0; i < 4; i++) {
        int gr = m0 + tm * 4 + i;
        if (gr < N_NODES) {
            if constexpr (N == 128) {
                *(float4*)(Y + gr * N + tn * 4) =
                    make_float4(acc[i][0], acc[i][1], acc[i][2], acc[i][3]);
                *(float4*)(Y + gr * N + 64 + tn * 4) =
                    make_float4(acc[i][4], acc[i][5], acc[i][6], acc[i][7]);
            } else {
                float s = g_dis[gr];
                *(float4*)(Y + gr * N + tn * 4) =
                    make_float4(acc[i][0] * s, acc[i][1] * s, acc[i][2] * s, acc[i][3] * s);
            }
        }
    }
}

// ---------------- layer-1 aggregation: warp per node, 128 ch ----------------
// h1 = relu( dis_i * (sum_e dis_re*h[row_e] + dis_i*h[i]) + b1 )
__global__ void k_agg1(const float* __restrict__ b1) {
    int w = (blockIdx.x * blockDim.x + threadIdx.x) >> 5;
    if (w >= N_NODES) return;
    int lane = threadIdx.x & 31;
    int beg = g_off[w], end = g_off[w + 1];
    const float4* h4 = (const float4*)g_h;
    float4 acc = make_float4(0.f, 0.f, 0.f, 0.f);

    for (int base = beg; base < end; base += 32) {
        int n = end - base; if (n > 32) n = 32;
        int ed = 0; float ds = 0.f;
        if (base + lane < end) {
            ed = g_csr[base + lane];
            ds = g_dis[ed];
        }
        int dsb = __float_as_int(ds);
        int j = 0;
        for (; j + 8 <= n; j += 8) {
            int r[8]; float m[8]; float4 v[8];
            #pragma unroll
            for (int u = 0; u < 8; u++) {
                r[u] = __shfl_sync(0xffffffffu, ed, j + u);
                m[u] = __int_as_float(__shfl_sync(0xffffffffu, dsb, j + u));
            }
            #pragma unroll
            for (int u = 0; u < 8; u++) v[u] = h4[r[u] * 32 + lane];
            #pragma unroll
            for (int u = 0; u < 8; u++) {
                acc.x = fmaf(v[u].x, m[u], acc.x);
                acc.y = fmaf(v[u].y, m[u], acc.y);
                acc.z = fmaf(v[u].z, m[u], acc.z);
                acc.w = fmaf(v[u].w, m[u], acc.w);
            }
        }
        if (j + 4 <= n) {
            int r[4]; float m[4]; float4 v[4];
            #pragma unroll
            for (int u = 0; u < 4; u++) {
                r[u] = __shfl_sync(0xffffffffu, ed, j + u);
                m[u] = __int_as_float(__shfl_sync(0xffffffffu, dsb, j + u));
            }
            #pragma unroll
            for (int u = 0; u < 4; u++) v[u] = h4[r[u] * 32 + lane];
            #pragma unroll
            for (int u = 0; u < 4; u++) {
                acc.x = fmaf(v[u].x, m[u], acc.x);
                acc.y = fmaf(v[u].y, m[u], acc.y);
                acc.z = fmaf(v[u].z, m[u], acc.z);
                acc.w = fmaf(v[u].w, m[u], acc.w);
            }
            j += 4;
        }
        for (; j < n; j++) {
            int   r0 = __shfl_sync(0xffffffffu, ed, j);
            float m0 = __int_as_float(__shfl_sync(0xffffffffu, dsb, j));
            float4 v0 = h4[r0 * 32 + lane];
            acc.x = fmaf(v0.x, m0, acc.x);
            acc.y = fmaf(v0.y, m0, acc.y);
            acc.z = fmaf(v0.z, m0, acc.z);
            acc.w = fmaf(v0.w, m0, acc.w);
        }
    }
    float di = g_dis[w];
    float4 hs = h4[w * 32 + lane];      // unscaled h_i
    float4 bb = ((const float4*)b1)[lane];
    acc.x = fmaf(hs.x, di, acc.x);
    acc.y = fmaf(hs.y, di, acc.y);
    acc.z = fmaf(hs.z, di, acc.z);
    acc.w = fmaf(hs.w, di, acc.w);
    float4 o;
    o.x = fmaxf(fmaf(acc.x, di, bb.x), 0.f);
    o.y = fmaxf(fmaf(acc.y, di, bb.y), 0.f);
    o.z = fmaxf(fmaf(acc.z, di, bb.z), 0.f);
    o.w = fmaxf(fmaf(acc.w, di, bb.w), 0.f);
    ((float4*)g_h1)[w * 32 + lane] = o;
}

// ---------------- layer-2 aggregation: warp per node, 64 ch -----------------
__global__ void k_agg2(const float* __restrict__ b2) {
    int w = (blockIdx.x * blockDim.x + threadIdx.x) >> 5;
    if (w >= N_NODES) return;
    int lane = threadIdx.x & 31;
    int beg = g_off[w], end = g_off[w + 1];
    const float2* z2 = (const float2*)g_z;
    float2 acc = make_float2(0.f, 0.f);

    for (int base = beg; base < end; base += 32) {
        int n = end - base; if (n > 32) n = 32;
        int ed = (base + lane < end) ? g_csr[base + lane] : 0;
        int j = 0;
        for (; j + 8 <= n; j += 8) {
            int r[8]; float2 v[8];
            #pragma unroll
            for (int u = 0; u < 8; u++) r[u] = __shfl_sync(0xffffffffu, ed, j + u);
            #pragma unroll
            for (int u = 0; u < 8; u++) v[u] = z2[r[u] * 32 + lane];
            acc.x += ((v[0].x + v[1].x) + (v[2].x + v[3].x)) + ((v[4].x + v[5].x) + (v[6].x + v[7].x));
            acc.y += ((v[0].y + v[1].y) + (v[2].y + v[3].y)) + ((v[4].y + v[5].y) + (v[6].y + v[7].y));
        }
        if (j + 4 <= n) {
            int r[4]; float2 v[4];
            #pragma unroll
            for (int u = 0; u < 4; u++) r[u] = __shfl_sync(0xffffffffu, ed, j + u);
            #pragma unroll
            for (int u = 0; u < 4; u++) v[u] = z2[r[u] * 32 + lane];
            acc.x += (v[0].x + v[1].x) + (v[2].x + v[3].x);
            acc.y += (v[0].y + v[1].y) + (v[2].y + v[3].y);
            j += 4;
        }
        for (; j < n; j++) {
            int r0 = __shfl_sync(0xffffffffu, ed, j);
            float2 v0 = z2[r0 * 32 + lane];
            acc.x += v0.x; acc.y += v0.y;
        }
    }
    float di = g_dis[w];
    float2 zs = z2[w * 32 + lane];
    float2 bb = ((const float2*)b2)[lane];
    float2 o;
    o.x = fmaf(acc.x + zs.x, di, bb.x);
    o.y = fmaf(acc.y + zs.y, di, bb.y);
    ((float2*)g_zf)[w * 32 + lane] = o;
}

// ---------------- decode: 16-lane group per label edge ----------------------
__global__ void k_decode(const int* __restrict__ src, const int* __restrict__ dst,
                         float* __restrict__ out) {
    int t = blockIdx.x * blockDim.x + threadIdx.x;
    int e = t >> 4;
    if (e >= N_LABEL) return;
    int sub = t & 15;
    int s = __ldg(src + e);
    int d = __ldg(dst + e);
    const float4* z4 = (const float4*)g_zf;
    float4 a = z4[s * 16 + sub];
    float4 b = z4[d * 16 + sub];
    float p = a.x * b.x + a.y * b.y + a.z * b.z + a.w * b.w;
    p += __shfl_xor_sync(0xffffffffu, p, 8, 16);
    p += __shfl_xor_sync(0xffffffffu, p, 4, 16);
    p += __shfl_xor_sync(0xffffffffu, p, 2, 16);
    p += __shfl_xor_sync(0xffffffffu, p, 1, 16);
    if (sub == 0) out[e] = p;
}

// ---------------- launch ----------------------------------------------------
extern "C" void kernel_launch(void* const* d_in, const int* in_sizes, int n_in,
                              void* d_out, int out_size) {
    const float* x  = (const float*)d_in[0];
    const float* W1 = (const float*)d_in[1];
    const float* b1 = (const float*)d_in[2];
    const float* W2 = (const float*)d_in[3];
    const float* b2 = (const float*)d_in[4];
    const int* edge_index = (const int*)d_in[5];
    const int* edge_label = (const int*)d_in[6];
    float* out = (float*)d_out;

    const int* erow = edge_index;
    const int* ecol = edge_index + N_EDGES;
    const int* lsrc = edge_label;
    const int* ldst = edge_label + N_LABEL;

    float *ph, *ph1, *pz;
    int   *pdeg;
    cudaGetSymbolAddress((void**)&ph,   g_h);
    cudaGetSymbolAddress((void**)&ph1,  g_h1);
    cudaGetSymbolAddress((void**)&pz,   g_z);
    cudaGetSymbolAddress((void**)&pdeg, g_degi);

    const int smem128 = (128 * 128 + 128 * 132) * sizeof(float);  // 133120
    const int smem64  = (128 * 64  + 128 * 132) * sizeof(float);  // 100352
    cudaFuncSetAttribute(k_gemm<128>, cudaFuncAttributeMaxDynamicSharedMemorySize, smem128);
    cudaFuncSetAttribute(k_gemm<64>,  cudaFuncAttributeMaxDynamicSharedMemorySize, smem64);

    const int deg_grid  = (N_EDGES / 4 + 255) / 256;
    const int fill_grid = (N_EDGES / 4 + 255) / 256;

    if (g_s2) {
        // fork: CSR build chain on side stream, gemm128 on capture stream
        cudaEventRecord(g_evA, 0);
        cudaStreamWaitEvent(g_s2, g_evA, 0);

        cudaMemsetAsync(pdeg, 0, N_NODES * sizeof(int), g_s2);
        k_deg<<<deg_grid, 256, 0, g_s2>>>((const int4*)ecol);
        k_scanA<<<NBLK, 256, 0, g_s2>>>();
        k_scanC<<<NBLK, 256, 0, g_s2>>>();
        k_fill<<<fill_grid, 256, 0, g_s2>>>((const int4*)erow, (const int4*)ecol);

        k_gemm<128><<<GEMM_TILES, 512, smem128>>>(x, W1, ph);

        cudaEventRecord(g_evB, g_s2);
        cudaStreamWaitEvent(0, g_evB, 0);
    } else {
        // fallback: fully sequential on the capture stream
        cudaMemsetAsync(pdeg, 0, N_NODES * sizeof(int), 0);
        k_deg<<<deg_grid, 256>>>((const int4*)ecol);
        k_scanA<<<NBLK, 256>>>();
        k_scanC<<<NBLK, 256>>>();
        k_fill<<<fill_grid, 256>>>((const int4*)erow, (const int4*)ecol);
        k_gemm<128><<<GEMM_TILES, 512, smem128>>>(x, W1, ph);
    }

    // layer-1 aggregation (applies per-edge dis[row] and final dis_i)
    k_agg1<<<(N_NODES * 32 + 255) / 256, 256>>>(b1);
    // layer 2
    k_gemm<64><<<GEMM_TILES, 512, smem64>>>(ph1, W2, pz);
    k_agg2<<<(N_NODES * 32 + 255) / 256, 256>>>(b2);
    // decode
    k_decode<<<(N_LABEL * 16 + 255) / 256, 256>>>(lsrc, ldst, out);
}

// round 8
// speedup vs baseline: 2.2204x; 1.0149x over previous
#include <cuda_runtime.h>
#include <cuda_fp16.h>

#define N_NODES 50000
#define N_EDGES 800000
#define N_LABEL 200000
#define NBLK 196           // ceil(50000/256)
#define GEMM_TILES 391     // ceil(50000/128)

// ---------------- scratch (device globals; no allocation allowed) ----------
__device__ int    g_degi[N_NODES];       // zero at load; re-zeroed by scanC
__device__ int    g_off[N_NODES + 1];
__device__ int    g_cur[N_NODES];
__device__ float  g_dis[N_NODES];        // (deg+1)^-1/2
__device__ int    g_bsum[256];
__device__ __align__(16) int    g_csr[N_EDGES];        // src row only
__device__ __align__(16) __half g_hh[N_NODES * 128];   // x @ W1, fp16 (UNSCALED)
__device__ __align__(16) float  g_h1[N_NODES * 128];   // relu layer-1 output
__device__ __align__(16) float  g_z [N_NODES * 64];    // (h1 @ W2) * dis[row]
__device__ __align__(16) float  g_zf[N_NODES * 64];    // final embeddings

// ---------------- side stream + events (created once at load time) ---------
static cudaStream_t g_s2 = 0;
static cudaEvent_t  g_evA = 0, g_evB = 0;
namespace {
struct StreamInit {
    StreamInit() {
        if (cudaStreamCreateWithFlags(&g_s2, cudaStreamNonBlocking) != cudaSuccess) { g_s2 = 0; return; }
        if (cudaEventCreateWithFlags(&g_evA, cudaEventDisableTiming) != cudaSuccess) { g_s2 = 0; return; }
        if (cudaEventCreateWithFlags(&g_evB, cudaEventDisableTiming) != cudaSuccess) { g_s2 = 0; return; }
    }
};
static StreamInit s_init;
}

// ---------------- degree (4 edges/thread) -----------------------------------
__global__ void k_deg(const int4* __restrict__ col4) {
    int i = blockIdx.x * blockDim.x + threadIdx.x;
    if (i < N_EDGES / 4) {
        int4 c = col4[i];
        atomicAdd(&g_degi[c.x], 1);
        atomicAdd(&g_degi[c.y], 1);
        atomicAdd(&g_degi[c.z], 1);
        atomicAdd(&g_degi[c.w], 1);
    }
}

// ---------------- scan stage A: per-block sums -------------------------------
__global__ void k_scanA() {
    int t = threadIdx.x, b = blockIdx.x;
    int i = b * 256 + t;
    int d = (i < N_NODES) ? g_degi[i] : 0;
    int v = d;
    #pragma unroll
    for (int o = 16; o; o >>= 1) v += __shfl_xor_sync(0xffffffffu, v, o);
    __shared__ int ws[8];
    if ((t & 31) == 0) ws[t >> 5] = v;
    __syncthreads();
    if (t == 0) {
        int s = 0;
        #pragma unroll
        for (int k = 0; k < 8; k++) s += ws[k];
        g_bsum[b] = s;
    }
}

// ---------------- scan stage C: offsets + norm; re-zeroes g_degi ------------
__global__ void k_scanC() {
    int t = threadIdx.x, b = blockIdx.x;
    int lane = t & 31, wid = t >> 5;
    __shared__ int ws[8];
    __shared__ int sb[256];

    {   // exclusive scan of the 196 block sums (every block redoes it; cheap)
        int d = (t < NBLK) ? g_bsum[t] : 0;
        int v = d;
        #pragma unroll
        for (int o = 1; o < 32; o <<= 1) {
            int u = __shfl_up_sync(0xffffffffu, v, o);
            if (lane >= o) v += u;
        }
        if (lane == 31) ws[wid] = v;
        __syncthreads();
        if (t == 0) {
            int run = 0;
            #pragma unroll
            for (int k = 0; k < 8; k++) { int tmp = ws[k]; ws[k] = run; run += tmp; }
        }
        __syncthreads();
        sb[t] = ws[wid] + v - d;
        __syncthreads();
    }
    int bpre = sb[b];

    int i = b * 256 + t;
    int d = (i < N_NODES) ? g_degi[i] : 0;
    int v = d;
    #pragma unroll
    for (int o = 1; o < 32; o <<= 1) {
        int u = __shfl_up_sync(0xffffffffu, v, o);
        if (lane >= o) v += u;
    }
    __syncthreads();
    if (lane == 31) ws[wid] = v;
    __syncthreads();
    if (t == 0) {
        int run = 0;
        #pragma unroll
        for (int k = 0; k < 8; k++) { int tmp = ws[k]; ws[k] = run; run += tmp; }
    }
    __syncthreads();
    if (i < N_NODES) {
        int pre = ws[wid] + (v - d) + bpre;
        g_off[i] = pre;
        g_cur[i] = pre;
        g_dis[i] = rsqrtf((float)d + 1.0f);
        g_degi[i] = 0;                       // restore invariant for next replay
        if (i == N_NODES - 1) g_off[N_NODES] = pre + d;
    }
}

// ---------------- CSR fill (counting sort by col, 4 edges/thread) -----------
__global__ void k_fill(const int4* __restrict__ row4, const int4* __restrict__ col4) {
    int i = blockIdx.x * blockDim.x + threadIdx.x;
    if (i >= N_EDGES / 4) return;
    int4 r = row4[i];
    int4 c = col4[i];
    int p0 = atomicAdd(&g_cur[c.x], 1);
    int p1 = atomicAdd(&g_cur[c.y], 1);
    int p2 = atomicAdd(&g_cur[c.z], 1);
    int p3 = atomicAdd(&g_cur[c.w], 1);
    g_csr[p0] = r.x;
    g_csr[p1] = r.y;
    g_csr[p2] = r.z;
    g_csr[p3] = r.w;
}

// ---------------- GEMM1: Hh = fp16(X @ W1) (unscaled) ------------------------
__global__ __launch_bounds__(512) void k_gemm1(const float* __restrict__ X,
                                               const float* __restrict__ W,
                                               __half* __restrict__ Y) {
    constexpr int N = 128, TILE_M = 128, LDX = 132;
    extern __shared__ float smem[];
    float* sW = smem;                 // 128 * 128
    float* sX = smem + 128 * N;       // 128 * 132

    const int tid = threadIdx.x;
    const int m0 = blockIdx.x * TILE_M;

    {
        const float4* W4 = (const float4*)W;
        float4* sW4 = (float4*)sW;
        #pragma unroll
        for (int i = tid; i < 128 * N / 4; i += 512) sW4[i] = W4[i];
    }
    {
        #pragma unroll
        for (int i = tid; i < TILE_M * 32; i += 512) {
            int rr = i >> 5, kk = i & 31;
            int gr = m0 + rr;
            float4 v = (gr < N_NODES) ? ((const float4*)X)[gr * 32 + kk]
                                      : make_float4(0.f, 0.f, 0.f, 0.f);
            *(float4*)(sX + rr * LDX + kk * 4) = v;
        }
    }
    __syncthreads();

    const int tn = tid & 15;
    const int tm = tid >> 4;

    float acc[4][8];
    #pragma unroll
    for (int i = 0; i < 4; i++)
        #pragma unroll
        for (int j = 0; j < 8; j++) acc[i][j] = 0.f;

    const float4* sW4 = (const float4*)sW;
    const float*  xb  = sX + tm * 4 * LDX;

    #pragma unroll 4
    for (int k = 0; k < 128; k++) {
        float a[4];
        #pragma unroll
        for (int i = 0; i < 4; i++) a[i] = xb[i * LDX + k];
        float4 b0 = sW4[k * 32 + tn];
        float4 b1 = sW4[k * 32 + tn + 16];
        #pragma unroll
        for (int i = 0; i < 4; i++) {
            acc[i][0] = fmaf(a[i], b0.x, acc[i][0]);
            acc[i][1] = fmaf(a[i], b0.y, acc[i][1]);
            acc[i][2] = fmaf(a[i], b0.z, acc[i][2]);
            acc[i][3] = fmaf(a[i], b0.w, acc[i][3]);
            acc[i][4] = fmaf(a[i], b1.x, acc[i][4]);
            acc[i][5] = fmaf(a[i], b1.y, acc[i][5]);
            acc[i][6] = fmaf(a[i], b1.z, acc[i][6]);
            acc[i][7] = fmaf(a[i], b1.w, acc[i][7]);
        }
    }

    #pragma unroll
    for (int i = 0; i < 4; i++) {
        int gr = m0 + tm * 4 + i;
        if (gr < N_NODES) {
            __half2 h0 = __floats2half2_rn(acc[i][0], acc[i][1]);
            __half2 h1 = __floats2half2_rn(acc[i][2], acc[i][3]);
            __half2 h2 = __floats2half2_rn(acc[i][4], acc[i][5]);
            __half2 h3 = __floats2half2_rn(acc[i][6], acc[i][7]);
            *(__half2*)(Y + gr * 128 + tn * 4)          = h0;
            *(__half2*)(Y + gr * 128 + tn * 4 + 2)      = h1;
            *(__half2*)(Y + gr * 128 + 64 + tn * 4)     = h2;
            *(__half2*)(Y + gr * 128 + 64 + tn * 4 + 2) = h3;
        }
    }
}

// ---------------- GEMM2: Z = (H1 @ W2) * dis[row] ----------------------------
__global__ __launch_bounds__(512) void k_gemm2(const float* __restrict__ X,
                                               const float* __restrict__ W,
                                               float* __restrict__ Y) {
    constexpr int N = 64, TILE_M = 128, LDX = 132;
    extern __shared__ float smem[];
    float* sW = smem;                 // 128 * 64
    float* sX = smem + 128 * N;       // 128 * 132

    const int tid = threadIdx.x;
    const int m0 = blockIdx.x * TILE_M;

    {
        const float4* W4 = (const float4*)W;
        float4* sW4 = (float4*)sW;
        #pragma unroll
        for (int i = tid; i < 128 * N / 4; i += 512) sW4[i] = W4[i];
    }
    {
        #pragma unroll
        for (int i = tid; i < TILE_M * 32; i += 512) {
            int rr = i >> 5, kk = i & 31;
            int gr = m0 + rr;
            float4 v = (gr < N_NODES) ? ((const float4*)X)[gr * 32 + kk]
                                      : make_float4(0.f, 0.f, 0.f, 0.f);
            *(float4*)(sX + rr * LDX + kk * 4) = v;
        }
    }
    __syncthreads();

    const int tn = tid & 15;
    const int tm = tid >> 4;

    float acc[4][4];
    #pragma unroll
    for (int i = 0; i < 4; i++)
        #pragma unroll
        for (int j = 0; j < 4; j++) acc[i][j] = 0.f;

    const float4* sW4 = (const float4*)sW;
    const float*  xb  = sX + tm * 4 * LDX;

    #pragma unroll 4
    for (int k = 0; k < 128; k++) {
        float a[4];
        #pragma unroll
        for (int i = 0; i < 4; i++) a[i] = xb[i * LDX + k];
        float4 b0 = sW4[k * 16 + tn];
        #pragma unroll
        for (int i = 0; i < 4; i++) {
            acc[i][0] = fmaf(a[i], b0.x, acc[i][0]);
            acc[i][1] = fmaf(a[i], b0.y, acc[i][1]);
            acc[i][2] = fmaf(a[i], b0.z, acc[i][2]);
            acc[i][3] = fmaf(a[i], b0.w, acc[i][3]);
        }
    }

    #pragma unroll
    for (int i = 0; i < 4; i++) {
        int gr = m0 + tm * 4 + i;
        if (gr < N_NODES) {
            float s = g_dis[gr];
            *(float4*)(Y + gr * N + tn * 4) =
                make_float4(acc[i][0] * s, acc[i][1] * s, acc[i][2] * s, acc[i][3] * s);
        }
    }
}

// ---------------- layer-1 aggregation: warp per node, 128 ch fp16 gather ----
// h1 = relu( dis_i * (sum_e dis_re*hh[row_e] + dis_i*hh[i]) + b1 )
__global__ void k_agg1(const float* __restrict__ b1) {
    int w = (blockIdx.x * blockDim.x + threadIdx.x) >> 5;
    if (w >= N_NODES) return;
    int lane = threadIdx.x & 31;
    int beg = g_off[w], end = g_off[w + 1];
    const uint2* hh = (const uint2*)g_hh;   // 4 fp16 ch per lane
    float4 acc = make_float4(0.f, 0.f, 0.f, 0.f);

    for (int base = beg; base < end; base += 32) {
        int n = end - base; if (n > 32) n = 32;
        int ed = 0; float ds = 0.f;
        if (base + lane < end) {
            ed = g_csr[base + lane];
            ds = g_dis[ed];
        }
        int dsb = __float_as_int(ds);
        int j = 0;
        for (; j + 8 <= n; j += 8) {
            int r[8]; float m[8]; uint2 v[8];
            #pragma unroll
            for (int u = 0; u < 8; u++) {
                r[u] = __shfl_sync(0xffffffffu, ed, j + u);
                m[u] = __int_as_float(__shfl_sync(0xffffffffu, dsb, j + u));
            }
            #pragma unroll
            for (int u = 0; u < 8; u++) v[u] = hh[r[u] * 32 + lane];
            #pragma unroll
            for (int u = 0; u < 8; u++) {
                float2 f0 = __half22float2(*(const __half2*)&v[u].x);
                float2 f1 = __half22float2(*(const __half2*)&v[u].y);
                acc.x = fmaf(f0.x, m[u], acc.x);
                acc.y = fmaf(f0.y, m[u], acc.y);
                acc.z = fmaf(f1.x, m[u], acc.z);
                acc.w = fmaf(f1.y, m[u], acc.w);
            }
        }
        if (j + 4 <= n) {
            int r[4]; float m[4]; uint2 v[4];
            #pragma unroll
            for (int u = 0; u < 4; u++) {
                r[u] = __shfl_sync(0xffffffffu, ed, j + u);
                m[u] = __int_as_float(__shfl_sync(0xffffffffu, dsb, j + u));
            }
            #pragma unroll
            for (int u = 0; u < 4; u++) v[u] = hh[r[u] * 32 + lane];
            #pragma unroll
            for (int u = 0; u < 4; u++) {
                float2 f0 = __half22float2(*(const __half2*)&v[u].x);
                float2 f1 = __half22float2(*(const __half2*)&v[u].y);
                acc.x = fmaf(f0.x, m[u], acc.x);
                acc.y = fmaf(f0.y, m[u], acc.y);
                acc.z = fmaf(f1.x, m[u], acc.z);
                acc.w = fmaf(f1.y, m[u], acc.w);
            }
            j += 4;
        }
        for (; j < n; j++) {
            int   r0 = __shfl_sync(0xffffffffu, ed, j);
            float m0 = __int_as_float(__shfl_sync(0xffffffffu, dsb, j));
            uint2 v0 = hh[r0 * 32 + lane];
            float2 f0 = __half22float2(*(const __half2*)&v0.x);
            float2 f1 = __half22float2(*(const __half2*)&v0.y);
            acc.x = fmaf(f0.x, m0, acc.x);
            acc.y = fmaf(f0.y, m0, acc.y);
            acc.z = fmaf(f1.x, m0, acc.z);
            acc.w = fmaf(f1.y, m0, acc.w);
        }
    }
    float di = g_dis[w];
    uint2 vs = hh[w * 32 + lane];
    float2 s0 = __half22float2(*(const __half2*)&vs.x);
    float2 s1 = __half22float2(*(const __half2*)&vs.y);
    float4 bb = ((const float4*)b1)[lane];
    acc.x = fmaf(s0.x, di, acc.x);
    acc.y = fmaf(s0.y, di, acc.y);
    acc.z = fmaf(s1.x, di, acc.z);
    acc.w = fmaf(s1.y, di, acc.w);
    float4 o;
    o.x = fmaxf(fmaf(acc.x, di, bb.x), 0.f);
    o.y = fmaxf(fmaf(acc.y, di, bb.y), 0.f);
    o.z = fmaxf(fmaf(acc.z, di, bb.z), 0.f);
    o.w = fmaxf(fmaf(acc.w, di, bb.w), 0.f);
    ((float4*)g_h1)[w * 32 + lane] = o;
}

// ---------------- layer-2 aggregation: warp per node, 64 ch fp32 ------------
__global__ void k_agg2(const float* __restrict__ b2) {
    int w = (blockIdx.x * blockDim.x + threadIdx.x) >> 5;
    if (w >= N_NODES) return;
    int lane = threadIdx.x & 31;
    int beg = g_off[w], end = g_off[w + 1];
    const float2* z2 = (const float2*)g_z;
    float2 acc = make_float2(0.f, 0.f);

    for (int base = beg; base < end; base += 32) {
        int n = end - base; if (n > 32) n = 32;
        int ed = (base + lane < end) ? g_csr[base + lane] : 0;
        int j = 0;
        for (; j + 8 <= n; j += 8) {
            int r[8]; float2 v[8];
            #pragma unroll
            for (int u = 0; u < 8; u++) r[u] = __shfl_sync(0xffffffffu, ed, j + u);
            #pragma unroll
            for (int u = 0; u < 8; u++) v[u] = z2[r[u] * 32 + lane];
            acc.x += ((v[0].x + v[1].x) + (v[2].x + v[3].x)) + ((v[4].x + v[5].x) + (v[6].x + v[7].x));
            acc.y += ((v[0].y + v[1].y) + (v[2].y + v[3].y)) + ((v[4].y + v[5].y) + (v[6].y + v[7].y));
        }
        if (j + 4 <= n) {
            int r[4]; float2 v[4];
            #pragma unroll
            for (int u = 0; u < 4; u++) r[u] = __shfl_sync(0xffffffffu, ed, j + u);
            #pragma unroll
            for (int u = 0; u < 4; u++) v[u] = z2[r[u] * 32 + lane];
            acc.x += (v[0].x + v[1].x) + (v[2].x + v[3].x);
            acc.y += (v[0].y + v[1].y) + (v[2].y + v[3].y);
            j += 4;
        }
        for (; j < n; j++) {
            int r0 = __shfl_sync(0xffffffffu, ed, j);
            float2 v0 = z2[r0 * 32 + lane];
            acc.x += v0.x; acc.y += v0.y;
        }
    }
    float di = g_dis[w];
    float2 zs = z2[w * 32 + lane];
    float2 bb = ((const float2*)b2)[lane];
    float2 o;
    o.x = fmaf(acc.x + zs.x, di, bb.x);
    o.y = fmaf(acc.y + zs.y, di, bb.y);
    ((float2*)g_zf)[w * 32 + lane] = o;
}

// ---------------- decode: 16-lane group per label edge ----------------------
__global__ void k_decode(const int* __restrict__ src, const int* __restrict__ dst,
                         float* __restrict__ out) {
    int t = blockIdx.x * blockDim.x + threadIdx.x;
    int e = t >> 4;
    if (e >= N_LABEL) return;
    int sub = t & 15;
    int s = __ldg(src + e);
    int d = __ldg(dst + e);
    const float4* z4 = (const float4*)g_zf;
    float4 a = z4[s * 16 + sub];
    float4 b = z4[d * 16 + sub];
    float p = a.x * b.x + a.y * b.y + a.z * b.z + a.w * b.w;
    p += __shfl_xor_sync(0xffffffffu, p, 8, 16);
    p += __shfl_xor_sync(0xffffffffu, p, 4, 16);
    p += __shfl_xor_sync(0xffffffffu, p, 2, 16);
    p += __shfl_xor_sync(0xffffffffu, p, 1, 16);
    if (sub == 0) out[e] = p;
}

// ---------------- launch ----------------------------------------------------
extern "C" void kernel_launch(void* const* d_in, const int* in_sizes, int n_in,
                              void* d_out, int out_size) {
    const float* x  = (const float*)d_in[0];
    const float* W1 = (const float*)d_in[1];
    const float* b1 = (const float*)d_in[2];
    const float* W2 = (const float*)d_in[3];
    const float* b2 = (const float*)d_in[4];
    const int* edge_index = (const int*)d_in[5];
    const int* edge_label = (const int*)d_in[6];
    float* out = (float*)d_out;

    const int* erow = edge_index;
    const int* ecol = edge_index + N_EDGES;
    const int* lsrc = edge_label;
    const int* ldst = edge_label + N_LABEL;

    __half* phh; float *ph1, *pz;
    cudaGetSymbolAddress((void**)&phh, g_hh);
    cudaGetSymbolAddress((void**)&ph1, g_h1);
    cudaGetSymbolAddress((void**)&pz,  g_z);

    const int smem128 = (128 * 128 + 128 * 132) * sizeof(float);  // 133120
    const int smem64  = (128 * 64  + 128 * 132) * sizeof(float);  // 100352
    cudaFuncSetAttribute(k_gemm1, cudaFuncAttributeMaxDynamicSharedMemorySize, smem128);
    cudaFuncSetAttribute(k_gemm2, cudaFuncAttributeMaxDynamicSharedMemorySize, smem64);

    const int deg_grid  = (N_EDGES / 4 + 255) / 256;
    const int fill_grid = (N_EDGES / 4 + 255) / 256;

    if (g_s2) {
        // fork: CSR build chain on side stream, gemm1 on capture stream
        cudaEventRecord(g_evA, 0);
        cudaStreamWaitEvent(g_s2, g_evA, 0);

        k_deg<<<deg_grid, 256, 0, g_s2>>>((const int4*)ecol);
        k_scanA<<<NBLK, 256, 0, g_s2>>>();
        k_scanC<<<NBLK, 256, 0, g_s2>>>();
        k_fill<<<fill_grid, 256, 0, g_s2>>>((const int4*)erow, (const int4*)ecol);

        k_gemm1<<<GEMM_TILES, 512, smem128>>>(x, W1, phh);

        cudaEventRecord(g_evB, g_s2);
        cudaStreamWaitEvent(0, g_evB, 0);
    } else {
        k_deg<<<deg_grid, 256>>>((const int4*)ecol);
        k_scanA<<<NBLK, 256>>>();
        k_scanC<<<NBLK, 256>>>();
        k_fill<<<fill_grid, 256>>>((const int4*)erow, (const int4*)ecol);
        k_gemm1<<<GEMM_TILES, 512, smem128>>>(x, W1, phh);
    }

    // layer-1 aggregation (fp16 gather, fp32 accumulate)
    k_agg1<<<(N_NODES * 32 + 255) / 256, 256>>>(b1);
    // layer 2
    k_gemm2<<<GEMM_TILES, 512, smem64>>>(ph1, W2, pz);
    k_agg2<<<(N_NODES * 32 + 255) / 256, 256>>>(b2);
    // decode
    k_decode<<<(N_LABEL * 16 + 255) / 256, 256>>>(lsrc, ldst, out);
}